// round 1
// baseline (speedup 1.0000x reference)
#include <cuda_runtime.h>
#include <math.h>

// Problem constants
#define BATCH 2
#define S_LEN 2048
#define HID   1024
#define NH    16
#define DH    64
#define ATT_SCALE 0.125f   // 64^-0.5

#define MTOT (BATCH * S_LEN)   // 4096 rows

// Scratch (allocation-free rule: __device__ globals)
__device__ float g_qkv[(size_t)MTOT * 3 * HID];  // [b*s, 3*1024]
__device__ float g_att[(size_t)MTOT * HID];      // [b*s, 1024]

// ---------------------------------------------------------------------------
// GEMM: C[M,N] = A[M,K] * B[N,K]^T (+ bias[n]) , all row-major, K % 8 == 0,
// M % 128 == 0, N % 128 == 0. 256 threads, 128x128 tile, 8x8 per thread.
// ---------------------------------------------------------------------------
__global__ __launch_bounds__(256) void gemm_tn_kernel(
    const float* __restrict__ A, const float* __restrict__ B,
    const float* __restrict__ bias, float* __restrict__ C,
    int M, int N, int K)
{
    __shared__ float As[8][128];
    __shared__ float Bs[8][128];

    const int tid = threadIdx.x;
    const int tx = tid & 15;
    const int ty = tid >> 4;
    const int m0 = blockIdx.y * 128;
    const int n0 = blockIdx.x * 128;

    // loader mapping: each thread loads one float4 of A and one of B per k-tile
    const int lr = tid >> 1;          // 0..127 row within tile
    const int lc = (tid & 1) * 4;     // 0 or 4

    float acc[8][8];
#pragma unroll
    for (int i = 0; i < 8; i++)
#pragma unroll
        for (int j = 0; j < 8; j++) acc[i][j] = 0.0f;

    const float* Arow = A + (size_t)(m0 + lr) * K + lc;
    const float* Brow = B + (size_t)(n0 + lr) * K + lc;

    for (int kt = 0; kt < K; kt += 8) {
        float4 av = *(const float4*)(Arow + kt);
        float4 bv = *(const float4*)(Brow + kt);
        __syncthreads();
        As[lc + 0][lr] = av.x; As[lc + 1][lr] = av.y;
        As[lc + 2][lr] = av.z; As[lc + 3][lr] = av.w;
        Bs[lc + 0][lr] = bv.x; Bs[lc + 1][lr] = bv.y;
        Bs[lc + 2][lr] = bv.z; Bs[lc + 3][lr] = bv.w;
        __syncthreads();

#pragma unroll
        for (int k = 0; k < 8; k++) {
            float a[8], bb[8];
            float4 a0 = *(const float4*)&As[k][ty * 8];
            float4 a1 = *(const float4*)&As[k][ty * 8 + 4];
            float4 b0 = *(const float4*)&Bs[k][tx * 8];
            float4 b1 = *(const float4*)&Bs[k][tx * 8 + 4];
            a[0]=a0.x; a[1]=a0.y; a[2]=a0.z; a[3]=a0.w;
            a[4]=a1.x; a[5]=a1.y; a[6]=a1.z; a[7]=a1.w;
            bb[0]=b0.x; bb[1]=b0.y; bb[2]=b0.z; bb[3]=b0.w;
            bb[4]=b1.x; bb[5]=b1.y; bb[6]=b1.z; bb[7]=b1.w;
#pragma unroll
            for (int i = 0; i < 8; i++)
#pragma unroll
                for (int j = 0; j < 8; j++)
                    acc[i][j] = fmaf(a[i], bb[j], acc[i][j]);
        }
    }

    // epilogue
    float bsv[8];
#pragma unroll
    for (int j = 0; j < 8; j++)
        bsv[j] = bias ? bias[n0 + tx * 8 + j] : 0.0f;

#pragma unroll
    for (int i = 0; i < 8; i++) {
        float* crow = C + (size_t)(m0 + ty * 8 + i) * N + n0 + tx * 8;
        float4 c0, c1;
        c0.x = acc[i][0] + bsv[0]; c0.y = acc[i][1] + bsv[1];
        c0.z = acc[i][2] + bsv[2]; c0.w = acc[i][3] + bsv[3];
        c1.x = acc[i][4] + bsv[4]; c1.y = acc[i][5] + bsv[5];
        c1.z = acc[i][6] + bsv[6]; c1.w = acc[i][7] + bsv[7];
        *(float4*)(crow)     = c0;
        *(float4*)(crow + 4) = c1;
    }
}

// ---------------------------------------------------------------------------
// Flash attention: one CTA handles 64 queries of one (b, head).
// grid = (S_LEN/64, BATCH*NH), 256 threads (16x16), 4x4 per thread.
// Q tile [64][65] padded, K/P tile [64][65] padded (aliased), V tile [64][64].
// ---------------------------------------------------------------------------
#define QPAD 65
#define SMEM_ATT ((2 * 64 * QPAD + 64 * 64) * (int)sizeof(float))

__global__ __launch_bounds__(256) void attn_kernel(
    const float* __restrict__ qkv, float* __restrict__ outp)
{
    extern __shared__ float sm[];
    float* Qs = sm;                  // [64][65]
    float* KP = sm + 64 * QPAD;      // [64][65]   K tile, then P tile
    float* Vs = sm + 2 * 64 * QPAD;  // [64][64]

    const int tid = threadIdx.x;
    const int tx = tid & 15;
    const int ty = tid >> 4;
    const int bh = blockIdx.y;
    const int b = bh >> 4;
    const int h = bh & 15;
    const int q0 = blockIdx.x * 64;

    // Load Q tile (once)
    for (int t = tid; t < 64 * 16; t += 256) {
        int r = t >> 4;
        int c4 = (t & 15) << 2;
        const float* src =
            qkv + ((size_t)(b * S_LEN + q0 + r) * 3) * HID + h * DH + c4;
        float4 v = *(const float4*)src;
        float* dst = Qs + r * QPAD + c4;
        dst[0] = v.x; dst[1] = v.y; dst[2] = v.z; dst[3] = v.w;
    }

    float mrow[4], lrow[4], acc[4][4];
#pragma unroll
    for (int i = 0; i < 4; i++) {
        mrow[i] = -1e30f;
        lrow[i] = 0.0f;
#pragma unroll
        for (int j = 0; j < 4; j++) acc[i][j] = 0.0f;
    }

    for (int kt = 0; kt < S_LEN; kt += 64) {
        __syncthreads();  // previous iter's KP/Vs reads done before overwrite
        // Load K and V tiles
        for (int t = tid; t < 64 * 16; t += 256) {
            int r = t >> 4;
            int c4 = (t & 15) << 2;
            size_t base =
                ((size_t)(b * S_LEN + kt + r) * 3) * HID + h * DH + c4;
            float4 kv = *(const float4*)(qkv + base + HID);
            float* kd = KP + r * QPAD + c4;
            kd[0] = kv.x; kd[1] = kv.y; kd[2] = kv.z; kd[3] = kv.w;
            float4 vv = *(const float4*)(qkv + base + 2 * HID);
            float* vd = Vs + r * 64 + c4;
            vd[0] = vv.x; vd[1] = vv.y; vd[2] = vv.z; vd[3] = vv.w;
        }
        __syncthreads();

        // S = Q * K^T (4x4 per thread, rank-1 updates over d)
        float sv[4][4];
#pragma unroll
        for (int i = 0; i < 4; i++)
#pragma unroll
            for (int j = 0; j < 4; j++) sv[i][j] = 0.0f;

#pragma unroll 8
        for (int d = 0; d < 64; d++) {
            float a[4], kk[4];
#pragma unroll
            for (int i = 0; i < 4; i++) a[i] = Qs[(ty * 4 + i) * QPAD + d];
#pragma unroll
            for (int j = 0; j < 4; j++) kk[j] = KP[(tx * 4 + j) * QPAD + d];
#pragma unroll
            for (int i = 0; i < 4; i++)
#pragma unroll
                for (int j = 0; j < 4; j++)
                    sv[i][j] = fmaf(a[i], kk[j], sv[i][j]);
        }

        // Online softmax per row (row spread across 16 lanes w/ same ty)
#pragma unroll
        for (int i = 0; i < 4; i++) {
            float mx = -1e30f;
#pragma unroll
            for (int j = 0; j < 4; j++) {
                sv[i][j] *= ATT_SCALE;
                mx = fmaxf(mx, sv[i][j]);
            }
#pragma unroll
            for (int off = 1; off < 16; off <<= 1)
                mx = fmaxf(mx, __shfl_xor_sync(0xffffffffu, mx, off));
            float mnew = fmaxf(mrow[i], mx);
            float corr = __expf(mrow[i] - mnew);
            float rsum = 0.0f;
#pragma unroll
            for (int j = 0; j < 4; j++) {
                float p = __expf(sv[i][j] - mnew);
                sv[i][j] = p;
                rsum += p;
            }
#pragma unroll
            for (int off = 1; off < 16; off <<= 1)
                rsum += __shfl_xor_sync(0xffffffffu, rsum, off);
            lrow[i] = lrow[i] * corr + rsum;
            mrow[i] = mnew;
#pragma unroll
            for (int j = 0; j < 4; j++) acc[i][j] *= corr;
        }

        __syncthreads();  // all S-compute reads of KP done
        // write P into KP (aliases K tile)
#pragma unroll
        for (int i = 0; i < 4; i++)
#pragma unroll
            for (int j = 0; j < 4; j++)
                KP[(ty * 4 + i) * QPAD + tx * 4 + j] = sv[i][j];
        __syncthreads();

        // O += P * V
#pragma unroll 4
        for (int kj = 0; kj < 64; kj++) {
            float p[4];
#pragma unroll
            for (int i = 0; i < 4; i++) p[i] = KP[(ty * 4 + i) * QPAD + kj];
            float4 v = *(const float4*)(Vs + kj * 64 + tx * 4);
#pragma unroll
            for (int i = 0; i < 4; i++) {
                acc[i][0] = fmaf(p[i], v.x, acc[i][0]);
                acc[i][1] = fmaf(p[i], v.y, acc[i][1]);
                acc[i][2] = fmaf(p[i], v.z, acc[i][2]);
                acc[i][3] = fmaf(p[i], v.w, acc[i][3]);
            }
        }
    }

    // Write out: out[b, s, h*64 + d]
#pragma unroll
    for (int i = 0; i < 4; i++) {
        float inv = 1.0f / lrow[i];
        int row = q0 + ty * 4 + i;
        float4 o;
        o.x = acc[i][0] * inv; o.y = acc[i][1] * inv;
        o.z = acc[i][2] * inv; o.w = acc[i][3] * inv;
        *(float4*)(outp + (size_t)(b * S_LEN + row) * HID + h * DH + tx * 4) = o;
    }
}

// ---------------------------------------------------------------------------
// Launch
// ---------------------------------------------------------------------------
extern "C" void kernel_launch(void* const* d_in, const int* in_sizes, int n_in,
                              void* d_out, int out_size)
{
    const float* x     = (const float*)d_in[0];  // [2, 2048, 1024]
    const float* w_qkv = (const float*)d_in[1];  // [3072, 1024]
    const float* w_out = (const float*)d_in[2];  // [1024, 1024]
    const float* b_out = (const float*)d_in[3];  // [1024]
    float* out = (float*)d_out;                  // [2, 2048, 1024]

    float* qkv_p = nullptr;
    float* att_p = nullptr;
    cudaGetSymbolAddress((void**)&qkv_p, g_qkv);
    cudaGetSymbolAddress((void**)&att_p, g_att);

    cudaFuncSetAttribute(attn_kernel,
                         cudaFuncAttributeMaxDynamicSharedMemorySize,
                         SMEM_ATT);

    // 1) qkv = x @ w_qkv^T     [4096, 3072]
    gemm_tn_kernel<<<dim3(3 * HID / 128, MTOT / 128), 256>>>(
        x, w_qkv, nullptr, qkv_p, MTOT, 3 * HID, HID);

    // 2) flash attention       [4096, 1024]
    attn_kernel<<<dim3(S_LEN / 64, BATCH * NH), 256, SMEM_ATT>>>(qkv_p, att_p);

    // 3) out = att @ w_out^T + b_out   [4096, 1024]
    gemm_tn_kernel<<<dim3(HID / 128, MTOT / 128), 256>>>(
        att_p, w_out, b_out, out, MTOT, HID, HID);
}

// round 4
// speedup vs baseline: 1.3987x; 1.3987x over previous
#include <cuda_runtime.h>
#include <math.h>
#include <stdint.h>

// Problem constants
#define BATCH 2
#define S_LEN 2048
#define HID   1024
#define NH    16
#define DH    64
#define ATT_SCALE 0.125f
#define MTOT (BATCH * S_LEN)   // 4096

// Scratch (allocation-free rule: __device__ globals)
__device__ float g_qkv[(size_t)MTOT * 3 * HID];
__device__ float g_att[(size_t)MTOT * HID];
__device__ float g_xr[(size_t)MTOT * HID];
__device__ float g_wqkvr[(size_t)3 * HID * HID];
__device__ float g_woutr[(size_t)HID * HID];

__device__ __forceinline__ uint32_t smem_u32(const void* p) {
    uint32_t a;
    asm("{ .reg .u64 t; cvta.to.shared.u64 t, %1; cvt.u32.u64 %0, t; }"
        : "=r"(a) : "l"(p));
    return a;
}
__device__ __forceinline__ float to_tf32(float x) {
    uint32_t u;
    asm("cvt.rn.tf32.f32 %0, %1;" : "=r"(u) : "f"(x));
    return __uint_as_float(u);
}

// ---------------------------------------------------------------------------
// tf32 rounding prepass
// ---------------------------------------------------------------------------
__global__ __launch_bounds__(256) void round_tf32_kernel(
    const float* __restrict__ src, float* __restrict__ dst, int n)
{
    int i = (blockIdx.x * blockDim.x + threadIdx.x) * 4;
    if (i < n) {
        float4 v = *(const float4*)(src + i);
        v.x = to_tf32(v.x); v.y = to_tf32(v.y);
        v.z = to_tf32(v.z); v.w = to_tf32(v.w);
        *(float4*)(dst + i) = v;
    }
}

// ---------------------------------------------------------------------------
// tf32 mma.sync GEMM: C[M,N] = A[M,K] * B[N,K]^T (+bias). Row-major.
// M,N % 128 == 0, K % 32 == 0. 256 threads, 128x128 tile, BK=32,
// 3-stage cp.async pipeline. Warp tile 64x32 via m16n8k8 fragments.
// ---------------------------------------------------------------------------
#define BM 128
#define BN 128
#define BK 32
#define BKP 36            // padded row stride (floats): conflict-free frag loads
#define NSTAGE 3
#define STAGEF (BM * BKP) // floats per operand stage

__device__ __forceinline__ void mma_tf32(float* c, const uint32_t* a,
                                         const uint32_t* b) {
    asm volatile(
        "mma.sync.aligned.m16n8k8.row.col.f32.tf32.tf32.f32 "
        "{%0,%1,%2,%3}, {%4,%5,%6,%7}, {%8,%9}, {%0,%1,%2,%3};"
        : "+f"(c[0]), "+f"(c[1]), "+f"(c[2]), "+f"(c[3])
        : "r"(a[0]), "r"(a[1]), "r"(a[2]), "r"(a[3]), "r"(b[0]), "r"(b[1]));
}

__global__ __launch_bounds__(256) void gemm_mma_kernel(
    const float* __restrict__ A, const float* __restrict__ B,
    const float* __restrict__ bias, float* __restrict__ C,
    int M, int N, int K)
{
    extern __shared__ float smf[];
    float* As = smf;
    float* Bs = smf + NSTAGE * STAGEF;

    const int tid = threadIdx.x;
    const int wid = tid >> 5;
    const int lane = tid & 31;
    const int g = lane >> 2;      // 0..7
    const int tig = lane & 3;     // 0..3
    const int wm = wid & 1;       // warp m index (0..1) -> 64 rows
    const int wn = wid >> 1;      // warp n index (0..3) -> 32 cols
    const int m0 = blockIdx.y * BM;
    const int n0 = blockIdx.x * BN;

    // global->smem loader mapping: 2 threads per 32-float row, 4 float4 each
    const int lrow = tid >> 1;
    const int lcol = (tid & 1) * 16;
    const float* Ag = A + (size_t)(m0 + lrow) * K + lcol;
    const float* Bg = B + (size_t)(n0 + lrow) * K + lcol;
    const uint32_t aDst = smem_u32(As + lrow * BKP + lcol);
    const uint32_t bDst = smem_u32(Bs + lrow * BKP + lcol);

    float acc[4][4][4];
#pragma unroll
    for (int mf = 0; mf < 4; mf++)
#pragma unroll
        for (int nf = 0; nf < 4; nf++)
#pragma unroll
            for (int r = 0; r < 4; r++) acc[mf][nf][r] = 0.0f;

    const int NT = K / BK;

#define ISSUE_STAGE(s, kt) do { \
    uint32_t _da = aDst + (s) * STAGEF * 4; \
    uint32_t _db = bDst + (s) * STAGEF * 4; \
    const float* _pa = Ag + (kt) * BK; \
    const float* _pb = Bg + (kt) * BK; \
    _Pragma("unroll") \
    for (int _i = 0; _i < 4; _i++) { \
        asm volatile("cp.async.cg.shared.global [%0], [%1], 16;" \
                     :: "r"(_da + _i * 16), "l"(_pa + _i * 4)); \
        asm volatile("cp.async.cg.shared.global [%0], [%1], 16;" \
                     :: "r"(_db + _i * 16), "l"(_pb + _i * 4)); \
    } \
    asm volatile("cp.async.commit_group;"); \
} while (0)

    // prologue: fill stages 0 and 1
    ISSUE_STAGE(0, 0);
    ISSUE_STAGE(1, 1);

    int stage = 0;
    for (int kt = 0; kt < NT; kt++) {
        if (kt == NT - 1) {
            asm volatile("cp.async.wait_group 0;");
        } else {
            asm volatile("cp.async.wait_group 1;");
        }
        __syncthreads();   // stage data visible to all; prior compute finished

        // prefetch stage kt+2 (its buffer was last read in compute(kt-1))
        if (kt + 2 < NT) {
            int s2 = stage + 2; if (s2 >= NSTAGE) s2 -= NSTAGE;
            ISSUE_STAGE(s2, kt + 2);
        }

        const float* as = As + stage * STAGEF + (wm * 64) * BKP;
        const float* bs = Bs + stage * STAGEF + (wn * 32) * BKP;

#pragma unroll
        for (int ks = 0; ks < 4; ks++) {
            const int kb = ks * 8;
            uint32_t af[4][4];
#pragma unroll
            for (int mf = 0; mf < 4; mf++) {
                const float* p = as + (mf * 16 + g) * BKP + kb + tig;
                af[mf][0] = __float_as_uint(p[0]);
                af[mf][1] = __float_as_uint(p[8 * BKP]);
                af[mf][2] = __float_as_uint(p[4]);
                af[mf][3] = __float_as_uint(p[8 * BKP + 4]);
            }
            uint32_t bf[4][2];
#pragma unroll
            for (int nf = 0; nf < 4; nf++) {
                const float* p = bs + (nf * 8 + g) * BKP + kb + tig;
                bf[nf][0] = __float_as_uint(p[0]);
                bf[nf][1] = __float_as_uint(p[4]);
            }
#pragma unroll
            for (int mf = 0; mf < 4; mf++)
#pragma unroll
                for (int nf = 0; nf < 4; nf++)
                    mma_tf32(acc[mf][nf], af[mf], bf[nf]);
        }

        stage = stage + 1; if (stage >= NSTAGE) stage -= NSTAGE;
    }

    // epilogue: c0,c1 at (row g, cols 2tig,2tig+1); c2,c3 at row g+8
#pragma unroll
    for (int mf = 0; mf < 4; mf++) {
        const int row0 = m0 + wm * 64 + mf * 16 + g;
#pragma unroll
        for (int nf = 0; nf < 4; nf++) {
            const int col = n0 + wn * 32 + nf * 8 + 2 * tig;
            float b0 = 0.0f, b1 = 0.0f;
            if (bias) { b0 = bias[col]; b1 = bias[col + 1]; }
            float2 v0 = {acc[mf][nf][0] + b0, acc[mf][nf][1] + b1};
            float2 v1 = {acc[mf][nf][2] + b0, acc[mf][nf][3] + b1};
            *(float2*)(C + (size_t)row0 * N + col) = v0;
            *(float2*)(C + (size_t)(row0 + 8) * N + col) = v1;
        }
    }
}

// ---------------------------------------------------------------------------
// Flash attention (fp32), output tf32-rounded for the out-projection MMA
// ---------------------------------------------------------------------------
#define QPAD 65
#define SMEM_ATT ((2 * 64 * QPAD + 64 * 64) * (int)sizeof(float))

__global__ __launch_bounds__(256) void attn_kernel(
    const float* __restrict__ qkv, float* __restrict__ outp)
{
    extern __shared__ float sm[];
    float* Qs = sm;
    float* KP = sm + 64 * QPAD;
    float* Vs = sm + 2 * 64 * QPAD;

    const int tid = threadIdx.x;
    const int tx = tid & 15;
    const int ty = tid >> 4;
    const int bh = blockIdx.y;
    const int b = bh >> 4;
    const int h = bh & 15;
    const int q0 = blockIdx.x * 64;

    for (int t = tid; t < 64 * 16; t += 256) {
        int r = t >> 4;
        int c4 = (t & 15) << 2;
        const float* src =
            qkv + ((size_t)(b * S_LEN + q0 + r) * 3) * HID + h * DH + c4;
        float4 v = *(const float4*)src;
        float* dst = Qs + r * QPAD + c4;
        dst[0] = v.x; dst[1] = v.y; dst[2] = v.z; dst[3] = v.w;
    }

    float mrow[4], lrow[4], acc[4][4];
#pragma unroll
    for (int i = 0; i < 4; i++) {
        mrow[i] = -1e30f;
        lrow[i] = 0.0f;
#pragma unroll
        for (int j = 0; j < 4; j++) acc[i][j] = 0.0f;
    }

    for (int kt = 0; kt < S_LEN; kt += 64) {
        __syncthreads();
        for (int t = tid; t < 64 * 16; t += 256) {
            int r = t >> 4;
            int c4 = (t & 15) << 2;
            size_t base =
                ((size_t)(b * S_LEN + kt + r) * 3) * HID + h * DH + c4;
            float4 kv = *(const float4*)(qkv + base + HID);
            float* kd = KP + r * QPAD + c4;
            kd[0] = kv.x; kd[1] = kv.y; kd[2] = kv.z; kd[3] = kv.w;
            float4 vv = *(const float4*)(qkv + base + 2 * HID);
            float* vd = Vs + r * 64 + c4;
            vd[0] = vv.x; vd[1] = vv.y; vd[2] = vv.z; vd[3] = vv.w;
        }
        __syncthreads();

        float sv[4][4];
#pragma unroll
        for (int i = 0; i < 4; i++)
#pragma unroll
            for (int j = 0; j < 4; j++) sv[i][j] = 0.0f;

#pragma unroll 8
        for (int d = 0; d < 64; d++) {
            float a[4], kk[4];
#pragma unroll
            for (int i = 0; i < 4; i++) a[i] = Qs[(ty * 4 + i) * QPAD + d];
#pragma unroll
            for (int j = 0; j < 4; j++) kk[j] = KP[(tx * 4 + j) * QPAD + d];
#pragma unroll
            for (int i = 0; i < 4; i++)
#pragma unroll
                for (int j = 0; j < 4; j++)
                    sv[i][j] = fmaf(a[i], kk[j], sv[i][j]);
        }

#pragma unroll
        for (int i = 0; i < 4; i++) {
            float mx = -1e30f;
#pragma unroll
            for (int j = 0; j < 4; j++) {
                sv[i][j] *= ATT_SCALE;
                mx = fmaxf(mx, sv[i][j]);
            }
#pragma unroll
            for (int off = 1; off < 16; off <<= 1)
                mx = fmaxf(mx, __shfl_xor_sync(0xffffffffu, mx, off));
            float mnew = fmaxf(mrow[i], mx);
            float corr = __expf(mrow[i] - mnew);
            float rsum = 0.0f;
#pragma unroll
            for (int j = 0; j < 4; j++) {
                float p = __expf(sv[i][j] - mnew);
                sv[i][j] = p;
                rsum += p;
            }
#pragma unroll
            for (int off = 1; off < 16; off <<= 1)
                rsum += __shfl_xor_sync(0xffffffffu, rsum, off);
            lrow[i] = lrow[i] * corr + rsum;
            mrow[i] = mnew;
#pragma unroll
            for (int j = 0; j < 4; j++) acc[i][j] *= corr;
        }

        __syncthreads();
#pragma unroll
        for (int i = 0; i < 4; i++)
#pragma unroll
            for (int j = 0; j < 4; j++)
                KP[(ty * 4 + i) * QPAD + tx * 4 + j] = sv[i][j];
        __syncthreads();

#pragma unroll 4
        for (int kj = 0; kj < 64; kj++) {
            float p[4];
#pragma unroll
            for (int i = 0; i < 4; i++) p[i] = KP[(ty * 4 + i) * QPAD + kj];
            float4 v = *(const float4*)(Vs + kj * 64 + tx * 4);
#pragma unroll
            for (int i = 0; i < 4; i++) {
                acc[i][0] = fmaf(p[i], v.x, acc[i][0]);
                acc[i][1] = fmaf(p[i], v.y, acc[i][1]);
                acc[i][2] = fmaf(p[i], v.z, acc[i][2]);
                acc[i][3] = fmaf(p[i], v.w, acc[i][3]);
            }
        }
    }

#pragma unroll
    for (int i = 0; i < 4; i++) {
        float inv = 1.0f / lrow[i];
        int row = q0 + ty * 4 + i;
        float4 o;
        o.x = to_tf32(acc[i][0] * inv);
        o.y = to_tf32(acc[i][1] * inv);
        o.z = to_tf32(acc[i][2] * inv);
        o.w = to_tf32(acc[i][3] * inv);
        *(float4*)(outp + (size_t)(b * S_LEN + row) * HID + h * DH + tx * 4) = o;
    }
}

// ---------------------------------------------------------------------------
// Launch
// ---------------------------------------------------------------------------
extern "C" void kernel_launch(void* const* d_in, const int* in_sizes, int n_in,
                              void* d_out, int out_size)
{
    const float* x     = (const float*)d_in[0];
    const float* w_qkv = (const float*)d_in[1];
    const float* w_out = (const float*)d_in[2];
    const float* b_out = (const float*)d_in[3];
    float* out = (float*)d_out;

    float *qkv_p, *att_p, *xr_p, *wqkvr_p, *woutr_p;
    cudaGetSymbolAddress((void**)&qkv_p, g_qkv);
    cudaGetSymbolAddress((void**)&att_p, g_att);
    cudaGetSymbolAddress((void**)&xr_p, g_xr);
    cudaGetSymbolAddress((void**)&wqkvr_p, g_wqkvr);
    cudaGetSymbolAddress((void**)&woutr_p, g_woutr);

    const int gemm_smem = NSTAGE * 2 * STAGEF * (int)sizeof(float);  // 110592
    cudaFuncSetAttribute(gemm_mma_kernel,
                         cudaFuncAttributeMaxDynamicSharedMemorySize, gemm_smem);
    cudaFuncSetAttribute(attn_kernel,
                         cudaFuncAttributeMaxDynamicSharedMemorySize, SMEM_ATT);

    // 0) tf32-round all MMA inputs (rn, unbiased)
    {
        int n1 = MTOT * HID;
        int n2 = 3 * HID * HID;
        int n3 = HID * HID;
        round_tf32_kernel<<<(n1 / 4 + 255) / 256, 256>>>(x, xr_p, n1);
        round_tf32_kernel<<<(n2 / 4 + 255) / 256, 256>>>(w_qkv, wqkvr_p, n2);
        round_tf32_kernel<<<(n3 / 4 + 255) / 256, 256>>>(w_out, woutr_p, n3);
    }

    // 1) qkv = x @ w_qkv^T   [4096, 3072]  (tf32 mma.sync)
    gemm_mma_kernel<<<dim3(3 * HID / BN, MTOT / BM), 256, gemm_smem>>>(
        xr_p, wqkvr_p, nullptr, qkv_p, MTOT, 3 * HID, HID);

    // 2) flash attention     [4096, 1024]  (fp32)
    attn_kernel<<<dim3(S_LEN / 64, BATCH * NH), 256, SMEM_ATT>>>(qkv_p, att_p);

    // 3) out = att @ w_out^T + b_out   [4096, 1024]  (tf32 mma.sync)
    gemm_mma_kernel<<<dim3(HID / BN, MTOT / BM), 256, gemm_smem>>>(
        att_p, woutr_p, b_out, out, MTOT, HID, HID);
}

// round 5
// speedup vs baseline: 1.7152x; 1.2263x over previous
#include <cuda_runtime.h>
#include <math.h>
#include <stdint.h>

// Problem constants
#define BATCH 2
#define S_LEN 2048
#define HID   1024
#define NH    16
#define DH    64
#define MTOT (BATCH * S_LEN)   // 4096
#define SCALE_LOG2E 0.18033688011112042f  // 0.125 * log2(e)

// Scratch (allocation-free rule: __device__ globals)
__device__ float g_qkv[(size_t)MTOT * 3 * HID];
__device__ float g_att[(size_t)MTOT * HID];
__device__ float g_xr[(size_t)MTOT * HID];
__device__ float g_wqkvr[(size_t)3 * HID * HID];
__device__ float g_woutr[(size_t)HID * HID];

__device__ __forceinline__ uint32_t smem_u32(const void* p) {
    uint32_t a;
    asm("{ .reg .u64 t; cvta.to.shared.u64 t, %1; cvt.u32.u64 %0, t; }"
        : "=r"(a) : "l"(p));
    return a;
}
__device__ __forceinline__ float to_tf32(float x) {
    uint32_t u;
    asm("cvt.rn.tf32.f32 %0, %1;" : "=r"(u) : "f"(x));
    return __uint_as_float(u);
}

// exp2 via FMA-pipe polynomial (no MUFU). Valid for x <= ~1, clamped below.
__device__ __forceinline__ float exp2_fast(float x) {
    x = fmaxf(x, -126.0f);
    float z = x + 12582912.0f;              // 1.5 * 2^23: round-to-nearest int
    int zi = __float_as_int(z);
    int ei = zi - 0x4B400000;               // integer part
    float fi = (float)ei;                    // exact
    float f = x - fi;                        // frac in [-0.5, 0.5]
    float p = 1.3333558146e-3f;
    p = fmaf(p, f, 9.6181291057e-3f);
    p = fmaf(p, f, 5.5504108664e-2f);
    p = fmaf(p, f, 2.4022650695e-1f);
    p = fmaf(p, f, 6.9314718056e-1f);
    p = fmaf(p, f, 1.0f);
    float s = __int_as_float((ei + 127) << 23);
    return p * s;
}

__device__ __forceinline__ void mma_tf32(float* c, const uint32_t* a,
                                         const uint32_t* b) {
    asm volatile(
        "mma.sync.aligned.m16n8k8.row.col.f32.tf32.tf32.f32 "
        "{%0,%1,%2,%3}, {%4,%5,%6,%7}, {%8,%9}, {%0,%1,%2,%3};"
        : "+f"(c[0]), "+f"(c[1]), "+f"(c[2]), "+f"(c[3])
        : "r"(a[0]), "r"(a[1]), "r"(a[2]), "r"(a[3]), "r"(b[0]), "r"(b[1]));
}

// ---------------------------------------------------------------------------
// tf32 rounding prepass
// ---------------------------------------------------------------------------
__global__ __launch_bounds__(256) void round_tf32_kernel(
    const float* __restrict__ src, float* __restrict__ dst, int n)
{
    int i = (blockIdx.x * blockDim.x + threadIdx.x) * 4;
    if (i < n) {
        float4 v = *(const float4*)(src + i);
        v.x = to_tf32(v.x); v.y = to_tf32(v.y);
        v.z = to_tf32(v.z); v.w = to_tf32(v.w);
        *(float4*)(dst + i) = v;
    }
}

// ---------------------------------------------------------------------------
// tf32 mma.sync GEMM: C[M,N] = A[M,K]*B[N,K]^T (+bias). 128x128 tile, BK=32.
// round_out: tf32-round outputs (for downstream MMA consumers).
// ---------------------------------------------------------------------------
#define BM 128
#define BN 128
#define BK 32
#define BKP 36
#define NSTAGE 3
#define STAGEF (BM * BKP)

__global__ __launch_bounds__(256) void gemm_mma_kernel(
    const float* __restrict__ A, const float* __restrict__ B,
    const float* __restrict__ bias, float* __restrict__ C,
    int M, int N, int K, int round_out)
{
    extern __shared__ float smf[];
    float* As = smf;
    float* Bs = smf + NSTAGE * STAGEF;

    const int tid = threadIdx.x;
    const int wid = tid >> 5;
    const int lane = tid & 31;
    const int g = lane >> 2;
    const int tig = lane & 3;
    const int wm = wid & 1;
    const int wn = wid >> 1;
    const int m0 = blockIdx.y * BM;
    const int n0 = blockIdx.x * BN;

    const int lrow = tid >> 1;
    const int lcol = (tid & 1) * 16;
    const float* Ag = A + (size_t)(m0 + lrow) * K + lcol;
    const float* Bg = B + (size_t)(n0 + lrow) * K + lcol;
    const uint32_t aDst = smem_u32(As + lrow * BKP + lcol);
    const uint32_t bDst = smem_u32(Bs + lrow * BKP + lcol);

    float acc[4][4][4];
#pragma unroll
    for (int mf = 0; mf < 4; mf++)
#pragma unroll
        for (int nf = 0; nf < 4; nf++)
#pragma unroll
            for (int r = 0; r < 4; r++) acc[mf][nf][r] = 0.0f;

    const int NT = K / BK;

#define ISSUE_STAGE(s, kt) do { \
    uint32_t _da = aDst + (s) * STAGEF * 4; \
    uint32_t _db = bDst + (s) * STAGEF * 4; \
    const float* _pa = Ag + (kt) * BK; \
    const float* _pb = Bg + (kt) * BK; \
    _Pragma("unroll") \
    for (int _i = 0; _i < 4; _i++) { \
        asm volatile("cp.async.cg.shared.global [%0], [%1], 16;" \
                     :: "r"(_da + _i * 16), "l"(_pa + _i * 4)); \
        asm volatile("cp.async.cg.shared.global [%0], [%1], 16;" \
                     :: "r"(_db + _i * 16), "l"(_pb + _i * 4)); \
    } \
    asm volatile("cp.async.commit_group;"); \
} while (0)

    ISSUE_STAGE(0, 0);
    ISSUE_STAGE(1, 1);

    int stage = 0;
    for (int kt = 0; kt < NT; kt++) {
        if (kt == NT - 1) {
            asm volatile("cp.async.wait_group 0;");
        } else {
            asm volatile("cp.async.wait_group 1;");
        }
        __syncthreads();

        if (kt + 2 < NT) {
            int s2 = stage + 2; if (s2 >= NSTAGE) s2 -= NSTAGE;
            ISSUE_STAGE(s2, kt + 2);
        }

        const float* as = As + stage * STAGEF + (wm * 64) * BKP;
        const float* bs = Bs + stage * STAGEF + (wn * 32) * BKP;

#pragma unroll
        for (int ks = 0; ks < 4; ks++) {
            const int kb = ks * 8;
            uint32_t af[4][4];
#pragma unroll
            for (int mf = 0; mf < 4; mf++) {
                const float* p = as + (mf * 16 + g) * BKP + kb + tig;
                af[mf][0] = __float_as_uint(p[0]);
                af[mf][1] = __float_as_uint(p[8 * BKP]);
                af[mf][2] = __float_as_uint(p[4]);
                af[mf][3] = __float_as_uint(p[8 * BKP + 4]);
            }
            uint32_t bf[4][2];
#pragma unroll
            for (int nf = 0; nf < 4; nf++) {
                const float* p = bs + (nf * 8 + g) * BKP + kb + tig;
                bf[nf][0] = __float_as_uint(p[0]);
                bf[nf][1] = __float_as_uint(p[4]);
            }
#pragma unroll
            for (int mf = 0; mf < 4; mf++)
#pragma unroll
                for (int nf = 0; nf < 4; nf++)
                    mma_tf32(acc[mf][nf], af[mf], bf[nf]);
        }

        stage = stage + 1; if (stage >= NSTAGE) stage -= NSTAGE;
    }

#pragma unroll
    for (int mf = 0; mf < 4; mf++) {
        const int row0 = m0 + wm * 64 + mf * 16 + g;
#pragma unroll
        for (int nf = 0; nf < 4; nf++) {
            const int col = n0 + wn * 32 + nf * 8 + 2 * tig;
            float b0 = 0.0f, b1 = 0.0f;
            if (bias) { b0 = bias[col]; b1 = bias[col + 1]; }
            float v00 = acc[mf][nf][0] + b0, v01 = acc[mf][nf][1] + b1;
            float v10 = acc[mf][nf][2] + b0, v11 = acc[mf][nf][3] + b1;
            if (round_out) {
                v00 = to_tf32(v00); v01 = to_tf32(v01);
                v10 = to_tf32(v10); v11 = to_tf32(v11);
            }
            float2 w0 = {v00, v01};
            float2 w1 = {v10, v11};
            *(float2*)(C + (size_t)row0 * N + col) = w0;
            *(float2*)(C + (size_t)(row0 + 8) * N + col) = w1;
        }
    }
}

// ---------------------------------------------------------------------------
// tf32 flash attention. One CTA = 128 queries of one (b,h). 256 threads,
// 8 warps x m16. K/V double-buffered cp.async. P staged per-warp in smem.
// Inputs (q,k,v) are pre-rounded to tf32 by the qkv GEMM epilogue.
// ---------------------------------------------------------------------------
#define LDQ 68   // row-accessed tiles: banks (4g+tig) conflict-free
#define LDV 72   // col-accessed V:     banks (8tig+g) conflict-free
#define SM_Q 0
#define SM_P (128 * LDQ)
#define SM_K (2 * 128 * LDQ)
#define SM_KSZ (64 * LDQ)
#define SM_V (SM_K + 2 * SM_KSZ)
#define SM_VSZ (64 * LDV)
#define SMEM_ATT ((SM_V + 2 * SM_VSZ) * 4)   // 141312 bytes

__global__ __launch_bounds__(256) void attn_tc_kernel(
    const float* __restrict__ qkv, float* __restrict__ outp)
{
    extern __shared__ float sm[];
    const int tid = threadIdx.x;
    const int lane = tid & 31;
    const int wid = tid >> 5;
    const int g = lane >> 2;
    const int tig = lane & 3;
    const int bh = blockIdx.y;
    const int b = bh >> 4;
    const int h = bh & 15;
    const int q0 = blockIdx.x * 128;

    const float* base = qkv + (size_t)b * S_LEN * 3 * HID + h * DH;

#define LOAD_KV(kt, buf) do { \
    _Pragma("unroll") \
    for (int _i = 0; _i < 4; _i++) { \
        int _t = tid + _i * 256; \
        int _r = _t >> 4, _c = (_t & 15) << 2; \
        const float* _sk = base + (size_t)((kt) * 64 + _r) * 3 * HID + HID + _c; \
        asm volatile("cp.async.cg.shared.global [%0], [%1], 16;" \
            :: "r"(smem_u32(sm + SM_K + (buf) * SM_KSZ + _r * LDQ + _c)), "l"(_sk)); \
        asm volatile("cp.async.cg.shared.global [%0], [%1], 16;" \
            :: "r"(smem_u32(sm + SM_V + (buf) * SM_VSZ + _r * LDV + _c)), "l"(_sk + HID)); \
    } \
} while (0)

    // group 0: Q + K0/V0 ; group 1: K1/V1
#pragma unroll
    for (int i = 0; i < 8; i++) {
        int t = tid + i * 256;
        int r = t >> 4, c = (t & 15) << 2;
        const float* sq = base + (size_t)(q0 + r) * 3 * HID + c;
        asm volatile("cp.async.cg.shared.global [%0], [%1], 16;"
            :: "r"(smem_u32(sm + SM_Q + r * LDQ + c)), "l"(sq));
    }
    LOAD_KV(0, 0);
    asm volatile("cp.async.commit_group;");
    LOAD_KV(1, 1);
    asm volatile("cp.async.commit_group;");

    float m0 = -1e30f, m1 = -1e30f, l0 = 0.0f, l1 = 0.0f;
    float oacc[8][4];
#pragma unroll
    for (int nf = 0; nf < 8; nf++)
#pragma unroll
        for (int r = 0; r < 4; r++) oacc[nf][r] = 0.0f;

    const float* Qw = sm + SM_Q + (wid * 16) * LDQ;
    float* Pw = sm + SM_P + (wid * 16) * LDQ;

    for (int kt = 0; kt < S_LEN / 64; kt++) {
        asm volatile("cp.async.wait_group 1;");
        __syncthreads();
        const float* Ks = sm + SM_K + (kt & 1) * SM_KSZ;
        const float* Vs = sm + SM_V + (kt & 1) * SM_VSZ;

        // ---- S = Q K^T (in log2-score domain later) ----
        float sacc[8][4];
#pragma unroll
        for (int nf = 0; nf < 8; nf++)
#pragma unroll
            for (int r = 0; r < 4; r++) sacc[nf][r] = 0.0f;

#pragma unroll
        for (int kf = 0; kf < 8; kf++) {
            const int kb = kf * 8;
            uint32_t a[4];
            const float* pa = Qw + g * LDQ + kb + tig;
            a[0] = __float_as_uint(pa[0]);
            a[1] = __float_as_uint(pa[8 * LDQ]);
            a[2] = __float_as_uint(pa[4]);
            a[3] = __float_as_uint(pa[8 * LDQ + 4]);
#pragma unroll
            for (int nf = 0; nf < 8; nf++) {
                const float* pb = Ks + (nf * 8 + g) * LDQ + kb + tig;
                uint32_t bf[2] = {__float_as_uint(pb[0]), __float_as_uint(pb[4])};
                mma_tf32(sacc[nf], a, bf);
            }
        }

        // ---- online softmax (rows g and g+8) ----
        float rmax0 = -1e30f, rmax1 = -1e30f;
#pragma unroll
        for (int nf = 0; nf < 8; nf++) {
#pragma unroll
            for (int r = 0; r < 4; r++) sacc[nf][r] *= SCALE_LOG2E;
            rmax0 = fmaxf(rmax0, fmaxf(sacc[nf][0], sacc[nf][1]));
            rmax1 = fmaxf(rmax1, fmaxf(sacc[nf][2], sacc[nf][3]));
        }
        rmax0 = fmaxf(rmax0, __shfl_xor_sync(0xffffffffu, rmax0, 1));
        rmax0 = fmaxf(rmax0, __shfl_xor_sync(0xffffffffu, rmax0, 2));
        rmax1 = fmaxf(rmax1, __shfl_xor_sync(0xffffffffu, rmax1, 1));
        rmax1 = fmaxf(rmax1, __shfl_xor_sync(0xffffffffu, rmax1, 2));

        const float mn0 = fmaxf(m0, rmax0);
        const float mn1 = fmaxf(m1, rmax1);
        const float corr0 = exp2_fast(m0 - mn0);
        const float corr1 = exp2_fast(m1 - mn1);
        m0 = mn0; m1 = mn1;

        float s0 = 0.0f, s1 = 0.0f;
        __syncwarp();
#pragma unroll
        for (int nf = 0; nf < 8; nf++) {
            float p0 = exp2_fast(sacc[nf][0] - mn0);
            float p1 = exp2_fast(sacc[nf][1] - mn0);
            float p2 = exp2_fast(sacc[nf][2] - mn1);
            float p3 = exp2_fast(sacc[nf][3] - mn1);
            s0 += p0 + p1;
            s1 += p2 + p3;
            float2 lo = {to_tf32(p0), to_tf32(p1)};
            float2 hi = {to_tf32(p2), to_tf32(p3)};
            *(float2*)(Pw + g * LDQ + nf * 8 + 2 * tig) = lo;
            *(float2*)(Pw + (g + 8) * LDQ + nf * 8 + 2 * tig) = hi;
        }
        s0 += __shfl_xor_sync(0xffffffffu, s0, 1);
        s0 += __shfl_xor_sync(0xffffffffu, s0, 2);
        s1 += __shfl_xor_sync(0xffffffffu, s1, 1);
        s1 += __shfl_xor_sync(0xffffffffu, s1, 2);
        l0 = l0 * corr0 + s0;
        l1 = l1 * corr1 + s1;
#pragma unroll
        for (int nf = 0; nf < 8; nf++) {
            oacc[nf][0] *= corr0; oacc[nf][1] *= corr0;
            oacc[nf][2] *= corr1; oacc[nf][3] *= corr1;
        }
        __syncwarp();   // P stores visible to all lanes of this warp

        // ---- O += P V ----
#pragma unroll
        for (int kf = 0; kf < 8; kf++) {
            const int kb = kf * 8;
            uint32_t a[4];
            const float* pa = Pw + g * LDQ + kb + tig;
            a[0] = __float_as_uint(pa[0]);
            a[1] = __float_as_uint(pa[8 * LDQ]);
            a[2] = __float_as_uint(pa[4]);
            a[3] = __float_as_uint(pa[8 * LDQ + 4]);
#pragma unroll
            for (int nf = 0; nf < 8; nf++) {
                const float* pb = Vs + (kb + tig) * LDV + nf * 8 + g;
                uint32_t bf[2] = {__float_as_uint(pb[0]),
                                  __float_as_uint(pb[4 * LDV])};
                mma_tf32(oacc[nf], a, bf);
            }
        }

        __syncthreads();   // all warps done reading this K/V buffer
        if (kt + 2 < S_LEN / 64) LOAD_KV(kt + 2, kt & 1);
        asm volatile("cp.async.commit_group;");
    }

    // ---- epilogue (tf32-rounded for out-projection) ----
    const float inv0 = 1.0f / l0;
    const float inv1 = 1.0f / l1;
    const int row0 = q0 + wid * 16 + g;
    float* od = outp + (size_t)(b * S_LEN + row0) * HID + h * DH;
#pragma unroll
    for (int nf = 0; nf < 8; nf++) {
        const int col = nf * 8 + 2 * tig;
        float2 v0 = {to_tf32(oacc[nf][0] * inv0), to_tf32(oacc[nf][1] * inv0)};
        float2 v1 = {to_tf32(oacc[nf][2] * inv1), to_tf32(oacc[nf][3] * inv1)};
        *(float2*)(od + col) = v0;
        *(float2*)(od + (size_t)8 * HID + col) = v1;
    }
}

// ---------------------------------------------------------------------------
// Launch
// ---------------------------------------------------------------------------
extern "C" void kernel_launch(void* const* d_in, const int* in_sizes, int n_in,
                              void* d_out, int out_size)
{
    const float* x     = (const float*)d_in[0];
    const float* w_qkv = (const float*)d_in[1];
    const float* w_out = (const float*)d_in[2];
    const float* b_out = (const float*)d_in[3];
    float* out = (float*)d_out;

    float *qkv_p, *att_p, *xr_p, *wqkvr_p, *woutr_p;
    cudaGetSymbolAddress((void**)&qkv_p, g_qkv);
    cudaGetSymbolAddress((void**)&att_p, g_att);
    cudaGetSymbolAddress((void**)&xr_p, g_xr);
    cudaGetSymbolAddress((void**)&wqkvr_p, g_wqkvr);
    cudaGetSymbolAddress((void**)&woutr_p, g_woutr);

    const int gemm_smem = NSTAGE * 2 * STAGEF * (int)sizeof(float);
    cudaFuncSetAttribute(gemm_mma_kernel,
                         cudaFuncAttributeMaxDynamicSharedMemorySize, gemm_smem);
    cudaFuncSetAttribute(attn_tc_kernel,
                         cudaFuncAttributeMaxDynamicSharedMemorySize, SMEM_ATT);

    // 0) tf32-round MMA inputs
    {
        int n1 = MTOT * HID;
        int n2 = 3 * HID * HID;
        int n3 = HID * HID;
        round_tf32_kernel<<<(n1 / 4 + 255) / 256, 256>>>(x, xr_p, n1);
        round_tf32_kernel<<<(n2 / 4 + 255) / 256, 256>>>(w_qkv, wqkvr_p, n2);
        round_tf32_kernel<<<(n3 / 4 + 255) / 256, 256>>>(w_out, woutr_p, n3);
    }

    // 1) qkv = x @ w_qkv^T  (outputs tf32-rounded for attention MMAs)
    gemm_mma_kernel<<<dim3(3 * HID / BN, MTOT / BM), 256, gemm_smem>>>(
        xr_p, wqkvr_p, nullptr, qkv_p, MTOT, 3 * HID, HID, 1);

    // 2) tf32 flash attention
    attn_tc_kernel<<<dim3(S_LEN / 128, BATCH * NH), 256, SMEM_ATT>>>(
        qkv_p, att_p);

    // 3) out = att @ w_out^T + b_out  (final output, NOT rounded)
    gemm_mma_kernel<<<dim3(HID / BN, MTOT / BM), 256, gemm_smem>>>(
        att_p, woutr_p, b_out, out, MTOT, HID, HID, 0);
}

// round 6
// speedup vs baseline: 2.2143x; 1.2910x over previous
#include <cuda_runtime.h>
#include <math.h>
#include <stdint.h>

// Problem constants
#define BATCH 2
#define S_LEN 2048
#define HID   1024
#define NH    16
#define DH    64
#define MTOT (BATCH * S_LEN)   // 4096
#define SCALE_LOG2E 0.18033688011112042f  // 0.125 * log2(e)

// Scratch (allocation-free rule: __device__ globals)
__device__ float g_qkv[(size_t)MTOT * 3 * HID];
__device__ float g_att[(size_t)MTOT * HID];
__device__ float g_xr[(size_t)MTOT * HID];
__device__ float g_wqkvr[(size_t)3 * HID * HID];
__device__ float g_woutr[(size_t)HID * HID];

__device__ __forceinline__ uint32_t smem_u32(const void* p) {
    uint32_t a;
    asm("{ .reg .u64 t; cvta.to.shared.u64 t, %1; cvt.u32.u64 %0, t; }"
        : "=r"(a) : "l"(p));
    return a;
}
__device__ __forceinline__ float to_tf32(float x) {
    uint32_t u;
    asm("cvt.rn.tf32.f32 %0, %1;" : "=r"(u) : "f"(x));
    return __uint_as_float(u);
}

// exp2 via FMA-pipe polynomial (no MUFU).
__device__ __forceinline__ float exp2_fast(float x) {
    x = fmaxf(x, -126.0f);
    float z = x + 12582912.0f;
    int ei = __float_as_int(z) - 0x4B400000;
    float f = x - (float)ei;
    float p = 1.3333558146e-3f;
    p = fmaf(p, f, 9.6181291057e-3f);
    p = fmaf(p, f, 5.5504108664e-2f);
    p = fmaf(p, f, 2.4022650695e-1f);
    p = fmaf(p, f, 6.9314718056e-1f);
    p = fmaf(p, f, 1.0f);
    return p * __int_as_float((ei + 127) << 23);
}

__device__ __forceinline__ void mma_tf32(float* c, const uint32_t* a,
                                         const uint32_t* b) {
    asm volatile(
        "mma.sync.aligned.m16n8k8.row.col.f32.tf32.tf32.f32 "
        "{%0,%1,%2,%3}, {%4,%5,%6,%7}, {%8,%9}, {%0,%1,%2,%3};"
        : "+f"(c[0]), "+f"(c[1]), "+f"(c[2]), "+f"(c[3])
        : "r"(a[0]), "r"(a[1]), "r"(a[2]), "r"(a[3]), "r"(b[0]), "r"(b[1]));
}

// ---------------------------------------------------------------------------
// tf32 rounding prepass
// ---------------------------------------------------------------------------
__global__ __launch_bounds__(256) void round_tf32_kernel(
    const float* __restrict__ src, float* __restrict__ dst, int n)
{
    int i = (blockIdx.x * blockDim.x + threadIdx.x) * 4;
    if (i < n) {
        float4 v = *(const float4*)(src + i);
        v.x = to_tf32(v.x); v.y = to_tf32(v.y);
        v.z = to_tf32(v.z); v.w = to_tf32(v.w);
        *(float4*)(dst + i) = v;
    }
}

// ---------------------------------------------------------------------------
// tf32 mma.sync GEMM: C[M,N] = A[M,K]*B[N,K]^T (+bias). CTA 128x128, BK=32,
// 128 threads, 4 warps, warp tile 64x64. 3-stage cp.async pipeline.
// ---------------------------------------------------------------------------
#define BM 128
#define BN 128
#define BK 32
#define BKP 36
#define NSTAGE 3
#define STAGEF (BM * BKP)

__global__ __launch_bounds__(128) void gemm_mma_kernel(
    const float* __restrict__ A, const float* __restrict__ B,
    const float* __restrict__ bias, float* __restrict__ C,
    int M, int N, int K, int round_out)
{
    extern __shared__ float smf[];
    float* As = smf;
    float* Bs = smf + NSTAGE * STAGEF;

    const int tid = threadIdx.x;
    const int wid = tid >> 5;
    const int lane = tid & 31;
    const int g = lane >> 2;
    const int tig = lane & 3;
    const int wm = wid & 1;       // 0..1 -> 64 rows
    const int wn = wid >> 1;      // 0..1 -> 64 cols
    const int m0 = blockIdx.y * BM;
    const int n0 = blockIdx.x * BN;

    // loader: each thread owns one row (BM=BN=128 = blockDim), 8 float4 per row
    const float* Ag = A + (size_t)(m0 + tid) * K;
    const float* Bg = B + (size_t)(n0 + tid) * K;
    const uint32_t aDst = smem_u32(As + tid * BKP);
    const uint32_t bDst = smem_u32(Bs + tid * BKP);

    float acc[4][8][4];
#pragma unroll
    for (int mf = 0; mf < 4; mf++)
#pragma unroll
        for (int nf = 0; nf < 8; nf++)
#pragma unroll
            for (int r = 0; r < 4; r++) acc[mf][nf][r] = 0.0f;

    const int NT = K / BK;

#define ISSUE_STAGE(s, kt) do { \
    uint32_t _da = aDst + (s) * STAGEF * 4; \
    uint32_t _db = bDst + (s) * STAGEF * 4; \
    const float* _pa = Ag + (kt) * BK; \
    const float* _pb = Bg + (kt) * BK; \
    _Pragma("unroll") \
    for (int _i = 0; _i < 8; _i++) { \
        asm volatile("cp.async.cg.shared.global [%0], [%1], 16;" \
                     :: "r"(_da + _i * 16), "l"(_pa + _i * 4)); \
        asm volatile("cp.async.cg.shared.global [%0], [%1], 16;" \
                     :: "r"(_db + _i * 16), "l"(_pb + _i * 4)); \
    } \
    asm volatile("cp.async.commit_group;"); \
} while (0)

    ISSUE_STAGE(0, 0);
    ISSUE_STAGE(1, 1);

    int stage = 0;
    for (int kt = 0; kt < NT; kt++) {
        if (kt == NT - 1) {
            asm volatile("cp.async.wait_group 0;");
        } else {
            asm volatile("cp.async.wait_group 1;");
        }
        __syncthreads();

        if (kt + 2 < NT) {
            int s2 = stage + 2; if (s2 >= NSTAGE) s2 -= NSTAGE;
            ISSUE_STAGE(s2, kt + 2);
        }

        const float* as = As + stage * STAGEF + (wm * 64) * BKP;
        const float* bs = Bs + stage * STAGEF + (wn * 64) * BKP;

#pragma unroll
        for (int ks = 0; ks < 4; ks++) {
            const int kb = ks * 8;
            uint32_t af[4][4];
#pragma unroll
            for (int mf = 0; mf < 4; mf++) {
                const float* p = as + (mf * 16 + g) * BKP + kb + tig;
                af[mf][0] = __float_as_uint(p[0]);
                af[mf][1] = __float_as_uint(p[8 * BKP]);
                af[mf][2] = __float_as_uint(p[4]);
                af[mf][3] = __float_as_uint(p[8 * BKP + 4]);
            }
            uint32_t bf[8][2];
#pragma unroll
            for (int nf = 0; nf < 8; nf++) {
                const float* p = bs + (nf * 8 + g) * BKP + kb + tig;
                bf[nf][0] = __float_as_uint(p[0]);
                bf[nf][1] = __float_as_uint(p[4]);
            }
#pragma unroll
            for (int mf = 0; mf < 4; mf++)
#pragma unroll
                for (int nf = 0; nf < 8; nf++)
                    mma_tf32(acc[mf][nf], af[mf], bf[nf]);
        }

        stage = stage + 1; if (stage >= NSTAGE) stage -= NSTAGE;
    }

#pragma unroll
    for (int mf = 0; mf < 4; mf++) {
        const int row0 = m0 + wm * 64 + mf * 16 + g;
#pragma unroll
        for (int nf = 0; nf < 8; nf++) {
            const int col = n0 + wn * 64 + nf * 8 + 2 * tig;
            float b0 = 0.0f, b1 = 0.0f;
            if (bias) { b0 = bias[col]; b1 = bias[col + 1]; }
            float v00 = acc[mf][nf][0] + b0, v01 = acc[mf][nf][1] + b1;
            float v10 = acc[mf][nf][2] + b0, v11 = acc[mf][nf][3] + b1;
            if (round_out) {
                v00 = to_tf32(v00); v01 = to_tf32(v01);
                v10 = to_tf32(v10); v11 = to_tf32(v11);
            }
            float2 w0 = {v00, v01};
            float2 w1 = {v10, v11};
            *(float2*)(C + (size_t)row0 * N + col) = w0;
            *(float2*)(C + (size_t)(row0 + 8) * N + col) = w1;
        }
    }
}

// ---------------------------------------------------------------------------
// tf32 flash attention. CTA = 64 queries of one (b,h), 128 threads (4 warps,
// m16 each). Q cached in registers (loaded once via P buffer). K/V double-
// buffered cp.async. smem 89KB -> 2 CTAs/SM.
// ---------------------------------------------------------------------------
#define LDQ 68
#define LDV 72
#define SM_P 0
#define SM_PSZ (64 * LDQ)
#define SM_K SM_PSZ
#define SM_KSZ (64 * LDQ)
#define SM_V (SM_K + 2 * SM_KSZ)
#define SM_VSZ (64 * LDV)
#define SMEM_ATT ((SM_V + 2 * SM_VSZ) * 4)   // 89088 bytes

__global__ __launch_bounds__(128) void attn_tc_kernel(
    const float* __restrict__ qkv, float* __restrict__ outp)
{
    extern __shared__ float sm[];
    const int tid = threadIdx.x;
    const int lane = tid & 31;
    const int wid = tid >> 5;
    const int g = lane >> 2;
    const int tig = lane & 3;
    const int bh = blockIdx.y;
    const int b = bh >> 4;
    const int h = bh & 15;
    const int q0 = blockIdx.x * 64;

    const float* base = qkv + (size_t)b * S_LEN * 3 * HID + h * DH;

#define LOAD_KV(kt, buf) do { \
    _Pragma("unroll") \
    for (int _i = 0; _i < 8; _i++) { \
        int _t = tid + _i * 128; \
        int _r = _t >> 4, _c = (_t & 15) << 2; \
        const float* _sk = base + (size_t)((kt) * 64 + _r) * 3 * HID + HID + _c; \
        asm volatile("cp.async.cg.shared.global [%0], [%1], 16;" \
            :: "r"(smem_u32(sm + SM_K + (buf) * SM_KSZ + _r * LDQ + _c)), "l"(_sk)); \
        asm volatile("cp.async.cg.shared.global [%0], [%1], 16;" \
            :: "r"(smem_u32(sm + SM_V + (buf) * SM_VSZ + _r * LDV + _c)), "l"(_sk + HID)); \
    } \
} while (0)

    // stage Q into P buffer (group 0), then K0/V0 (g1), K1/V1 (g2)
#pragma unroll
    for (int i = 0; i < 8; i++) {
        int t = tid + i * 128;
        int r = t >> 4, c = (t & 15) << 2;
        const float* sq = base + (size_t)(q0 + r) * 3 * HID + c;
        asm volatile("cp.async.cg.shared.global [%0], [%1], 16;"
            :: "r"(smem_u32(sm + SM_P + r * LDQ + c)), "l"(sq));
    }
    asm volatile("cp.async.commit_group;");
    LOAD_KV(0, 0);
    asm volatile("cp.async.commit_group;");
    LOAD_KV(1, 1);
    asm volatile("cp.async.commit_group;");

    float* Pw = sm + SM_P + (wid * 16) * LDQ;

    // Q fragments -> registers (loop-invariant)
    asm volatile("cp.async.wait_group 2;");
    __syncthreads();
    uint32_t qf[8][4];
#pragma unroll
    for (int kf = 0; kf < 8; kf++) {
        const float* pa = Pw + g * LDQ + kf * 8 + tig;
        qf[kf][0] = __float_as_uint(pa[0]);
        qf[kf][1] = __float_as_uint(pa[8 * LDQ]);
        qf[kf][2] = __float_as_uint(pa[4]);
        qf[kf][3] = __float_as_uint(pa[8 * LDQ + 4]);
    }

    float m0 = -1e30f, m1 = -1e30f, l0 = 0.0f, l1 = 0.0f;
    float oacc[8][4];
#pragma unroll
    for (int nf = 0; nf < 8; nf++)
#pragma unroll
        for (int r = 0; r < 4; r++) oacc[nf][r] = 0.0f;

    for (int kt = 0; kt < S_LEN / 64; kt++) {
        asm volatile("cp.async.wait_group 1;");
        __syncthreads();
        const float* Ks = sm + SM_K + (kt & 1) * SM_KSZ;
        const float* Vs = sm + SM_V + (kt & 1) * SM_VSZ;

        // ---- S = Q K^T ----
        float sacc[8][4];
#pragma unroll
        for (int nf = 0; nf < 8; nf++)
#pragma unroll
            for (int r = 0; r < 4; r++) sacc[nf][r] = 0.0f;

#pragma unroll
        for (int kf = 0; kf < 8; kf++) {
            const int kb = kf * 8;
#pragma unroll
            for (int nf = 0; nf < 8; nf++) {
                const float* pb = Ks + (nf * 8 + g) * LDQ + kb + tig;
                uint32_t bf[2] = {__float_as_uint(pb[0]), __float_as_uint(pb[4])};
                mma_tf32(sacc[nf], qf[kf], bf);
            }
        }

        // ---- online softmax (rows g and g+8) ----
        float rmax0 = -1e30f, rmax1 = -1e30f;
#pragma unroll
        for (int nf = 0; nf < 8; nf++) {
#pragma unroll
            for (int r = 0; r < 4; r++) sacc[nf][r] *= SCALE_LOG2E;
            rmax0 = fmaxf(rmax0, fmaxf(sacc[nf][0], sacc[nf][1]));
            rmax1 = fmaxf(rmax1, fmaxf(sacc[nf][2], sacc[nf][3]));
        }
        rmax0 = fmaxf(rmax0, __shfl_xor_sync(0xffffffffu, rmax0, 1));
        rmax0 = fmaxf(rmax0, __shfl_xor_sync(0xffffffffu, rmax0, 2));
        rmax1 = fmaxf(rmax1, __shfl_xor_sync(0xffffffffu, rmax1, 1));
        rmax1 = fmaxf(rmax1, __shfl_xor_sync(0xffffffffu, rmax1, 2));

        const float mn0 = fmaxf(m0, rmax0);
        const float mn1 = fmaxf(m1, rmax1);
        const float corr0 = exp2_fast(m0 - mn0);
        const float corr1 = exp2_fast(m1 - mn1);
        m0 = mn0; m1 = mn1;

        float s0 = 0.0f, s1 = 0.0f;
        __syncwarp();
#pragma unroll
        for (int nf = 0; nf < 8; nf++) {
            float p0 = exp2_fast(sacc[nf][0] - mn0);
            float p1 = exp2_fast(sacc[nf][1] - mn0);
            float p2 = exp2_fast(sacc[nf][2] - mn1);
            float p3 = exp2_fast(sacc[nf][3] - mn1);
            s0 += p0 + p1;
            s1 += p2 + p3;
            float2 lo = {to_tf32(p0), to_tf32(p1)};
            float2 hi = {to_tf32(p2), to_tf32(p3)};
            *(float2*)(Pw + g * LDQ + nf * 8 + 2 * tig) = lo;
            *(float2*)(Pw + (g + 8) * LDQ + nf * 8 + 2 * tig) = hi;
        }
        s0 += __shfl_xor_sync(0xffffffffu, s0, 1);
        s0 += __shfl_xor_sync(0xffffffffu, s0, 2);
        s1 += __shfl_xor_sync(0xffffffffu, s1, 1);
        s1 += __shfl_xor_sync(0xffffffffu, s1, 2);
        l0 = l0 * corr0 + s0;
        l1 = l1 * corr1 + s1;
#pragma unroll
        for (int nf = 0; nf < 8; nf++) {
            oacc[nf][0] *= corr0; oacc[nf][1] *= corr0;
            oacc[nf][2] *= corr1; oacc[nf][3] *= corr1;
        }
        __syncwarp();

        // ---- O += P V ----
#pragma unroll
        for (int kf = 0; kf < 8; kf++) {
            const int kb = kf * 8;
            uint32_t a[4];
            const float* pa = Pw + g * LDQ + kb + tig;
            a[0] = __float_as_uint(pa[0]);
            a[1] = __float_as_uint(pa[8 * LDQ]);
            a[2] = __float_as_uint(pa[4]);
            a[3] = __float_as_uint(pa[8 * LDQ + 4]);
#pragma unroll
            for (int nf = 0; nf < 8; nf++) {
                const float* pb = Vs + (kb + tig) * LDV + nf * 8 + g;
                uint32_t bf[2] = {__float_as_uint(pb[0]),
                                  __float_as_uint(pb[4 * LDV])};
                mma_tf32(oacc[nf], a, bf);
            }
        }

        __syncthreads();
        if (kt + 2 < S_LEN / 64) LOAD_KV(kt + 2, kt & 1);
        asm volatile("cp.async.commit_group;");
    }

    // ---- epilogue (tf32-rounded for out-projection) ----
    const float inv0 = 1.0f / l0;
    const float inv1 = 1.0f / l1;
    const int row0 = q0 + wid * 16 + g;
    float* od = outp + (size_t)(b * S_LEN + row0) * HID + h * DH;
#pragma unroll
    for (int nf = 0; nf < 8; nf++) {
        const int col = nf * 8 + 2 * tig;
        float2 v0 = {to_tf32(oacc[nf][0] * inv0), to_tf32(oacc[nf][1] * inv0)};
        float2 v1 = {to_tf32(oacc[nf][2] * inv1), to_tf32(oacc[nf][3] * inv1)};
        *(float2*)(od + col) = v0;
        *(float2*)(od + (size_t)8 * HID + col) = v1;
    }
}

// ---------------------------------------------------------------------------
// Launch
// ---------------------------------------------------------------------------
extern "C" void kernel_launch(void* const* d_in, const int* in_sizes, int n_in,
                              void* d_out, int out_size)
{
    const float* x     = (const float*)d_in[0];
    const float* w_qkv = (const float*)d_in[1];
    const float* w_out = (const float*)d_in[2];
    const float* b_out = (const float*)d_in[3];
    float* out = (float*)d_out;

    float *qkv_p, *att_p, *xr_p, *wqkvr_p, *woutr_p;
    cudaGetSymbolAddress((void**)&qkv_p, g_qkv);
    cudaGetSymbolAddress((void**)&att_p, g_att);
    cudaGetSymbolAddress((void**)&xr_p, g_xr);
    cudaGetSymbolAddress((void**)&wqkvr_p, g_wqkvr);
    cudaGetSymbolAddress((void**)&woutr_p, g_woutr);

    const int gemm_smem = NSTAGE * 2 * STAGEF * (int)sizeof(float);
    cudaFuncSetAttribute(gemm_mma_kernel,
                         cudaFuncAttributeMaxDynamicSharedMemorySize, gemm_smem);
    cudaFuncSetAttribute(attn_tc_kernel,
                         cudaFuncAttributeMaxDynamicSharedMemorySize, SMEM_ATT);

    // 0) tf32-round MMA inputs
    {
        int n1 = MTOT * HID;
        int n2 = 3 * HID * HID;
        int n3 = HID * HID;
        round_tf32_kernel<<<(n1 / 4 + 255) / 256, 256>>>(x, xr_p, n1);
        round_tf32_kernel<<<(n2 / 4 + 255) / 256, 256>>>(w_qkv, wqkvr_p, n2);
        round_tf32_kernel<<<(n3 / 4 + 255) / 256, 256>>>(w_out, woutr_p, n3);
    }

    // 1) qkv = x @ w_qkv^T  (outputs tf32-rounded for attention MMAs)
    gemm_mma_kernel<<<dim3(3 * HID / BN, MTOT / BM), 128, gemm_smem>>>(
        xr_p, wqkvr_p, nullptr, qkv_p, MTOT, 3 * HID, HID, 1);

    // 2) tf32 flash attention (64-query CTAs, Q in registers)
    attn_tc_kernel<<<dim3(S_LEN / 64, BATCH * NH), 128, SMEM_ATT>>>(
        qkv_p, att_p);

    // 3) out = att @ w_out^T + b_out  (final output, NOT rounded)
    gemm_mma_kernel<<<dim3(HID / BN, MTOT / BM), 128, gemm_smem>>>(
        att_p, woutr_p, b_out, out, MTOT, HID, HID, 0);
}

// round 7
// speedup vs baseline: 2.6536x; 1.1984x over previous
#include <cuda_runtime.h>
#include <math.h>
#include <stdint.h>

// Problem constants
#define BATCH 2
#define S_LEN 2048
#define HID   1024
#define NH    16
#define DH    64
#define MTOT (BATCH * S_LEN)   // 4096
#define SCALE_LOG2E 0.18033688011112042f  // 0.125 * log2(e)

// Scratch (allocation-free rule: __device__ globals)
__device__ float g_qkv[(size_t)MTOT * 3 * HID];   // q,k parts only
__device__ float g_vt[(size_t)BATCH * NH * DH * S_LEN];  // V transposed [b,h,d,s]
__device__ float g_att[(size_t)MTOT * HID];
__device__ float g_xr[(size_t)MTOT * HID];
__device__ float g_wqkvr[(size_t)3 * HID * HID];
__device__ float g_woutr[(size_t)HID * HID];

__device__ __forceinline__ uint32_t smem_u32(const void* p) {
    uint32_t a;
    asm("{ .reg .u64 t; cvta.to.shared.u64 t, %1; cvt.u32.u64 %0, t; }"
        : "=r"(a) : "l"(p));
    return a;
}
__device__ __forceinline__ float to_tf32(float x) {
    uint32_t u;
    asm("cvt.rn.tf32.f32 %0, %1;" : "=r"(u) : "f"(x));
    return __uint_as_float(u);
}

// exp2 via FMA-pipe polynomial (no MUFU).
__device__ __forceinline__ float exp2_fast(float x) {
    x = fmaxf(x, -126.0f);
    float z = x + 12582912.0f;
    int ei = __float_as_int(z) - 0x4B400000;
    float f = x - (float)ei;
    float p = 1.3333558146e-3f;
    p = fmaf(p, f, 9.6181291057e-3f);
    p = fmaf(p, f, 5.5504108664e-2f);
    p = fmaf(p, f, 2.4022650695e-1f);
    p = fmaf(p, f, 6.9314718056e-1f);
    p = fmaf(p, f, 1.0f);
    return p * __int_as_float((ei + 127) << 23);
}

__device__ __forceinline__ void mma_tf32(float* c, const uint32_t* a,
                                         const uint32_t* b) {
    asm volatile(
        "mma.sync.aligned.m16n8k8.row.col.f32.tf32.tf32.f32 "
        "{%0,%1,%2,%3}, {%4,%5,%6,%7}, {%8,%9}, {%0,%1,%2,%3};"
        : "+f"(c[0]), "+f"(c[1]), "+f"(c[2]), "+f"(c[3])
        : "r"(a[0]), "r"(a[1]), "r"(a[2]), "r"(a[3]), "r"(b[0]), "r"(b[1]));
}
__device__ __forceinline__ void ldm_x4(uint32_t* r, uint32_t addr) {
    asm volatile(
        "ldmatrix.sync.aligned.m8n8.x4.shared.b16 {%0,%1,%2,%3}, [%4];"
        : "=r"(r[0]), "=r"(r[1]), "=r"(r[2]), "=r"(r[3]) : "r"(addr));
}

// ---------------------------------------------------------------------------
// tf32 rounding prepass
// ---------------------------------------------------------------------------
__global__ __launch_bounds__(256) void round_tf32_kernel(
    const float* __restrict__ src, float* __restrict__ dst, int n)
{
    int i = (blockIdx.x * blockDim.x + threadIdx.x) * 4;
    if (i < n) {
        float4 v = *(const float4*)(src + i);
        v.x = to_tf32(v.x); v.y = to_tf32(v.y);
        v.z = to_tf32(v.z); v.w = to_tf32(v.w);
        *(float4*)(dst + i) = v;
    }
}

// ---------------------------------------------------------------------------
// tf32 mma.sync GEMM: C[M,N] = A[M,K]*B[N,K]^T (+bias). CTA 128x128, BK=32,
// 256 threads, 8 warps, warp tile 64x32. ldmatrix fragment loads.
// vt != nullptr: cols >= 2048 are written transposed to vt[b,h,d,s] instead.
// ---------------------------------------------------------------------------
#define BM 128
#define BN 128
#define BK 32
#define BKP 36
#define NSTAGE 3
#define STAGEF (BM * BKP)

__global__ __launch_bounds__(256) void gemm_mma_kernel(
    const float* __restrict__ A, const float* __restrict__ B,
    const float* __restrict__ bias, float* __restrict__ C,
    float* __restrict__ vt, int M, int N, int K, int round_out)
{
    extern __shared__ float smf[];
    float* As = smf;
    float* Bs = smf + NSTAGE * STAGEF;

    const int tid = threadIdx.x;
    const int wid = tid >> 5;
    const int lane = tid & 31;
    const int g = lane >> 2;
    const int tig = lane & 3;
    const int ri = lane & 7;
    const int tq = lane >> 3;     // ldmatrix tile quad 0..3
    const int wm = wid & 1;       // 0..1 -> 64 rows
    const int wn = wid >> 1;      // 0..3 -> 32 cols
    const int m0 = blockIdx.y * BM;
    const int n0 = blockIdx.x * BN;

    const int lrow = tid >> 1;
    const int lcol = (tid & 1) * 16;
    const float* Ag = A + (size_t)(m0 + lrow) * K + lcol;
    const float* Bg = B + (size_t)(n0 + lrow) * K + lcol;
    const uint32_t aDst = smem_u32(As + lrow * BKP + lcol);
    const uint32_t bDst = smem_u32(Bs + lrow * BKP + lcol);

    // ldmatrix per-lane address offsets (bytes)
    // A-frag (m16k8): t0 rows0-7 k0-3, t1 rows8-15 k0-3, t2 rows0-7 k4-7, t3 rows8-15 k4-7
    const uint32_t aLane = (uint32_t)(((tq & 1) * 8 + ri) * BKP) * 4 + (tq >> 1) * 16;
    // B-frag pair (two n8 blocks): t0 n0-7 k0-3, t1 n0-7 k4-7, t2 n8-15 k0-3, t3 n8-15 k4-7
    const uint32_t bLane = (uint32_t)(((tq >> 1) * 8 + ri) * BKP) * 4 + (tq & 1) * 16;
    const uint32_t aBase0 = smem_u32(As) + (uint32_t)(wm * 64 * BKP) * 4 + aLane;
    const uint32_t bBase0 = smem_u32(Bs) + (uint32_t)(wn * 32 * BKP) * 4 + bLane;

    float acc[4][4][4];
#pragma unroll
    for (int mf = 0; mf < 4; mf++)
#pragma unroll
        for (int nf = 0; nf < 4; nf++)
#pragma unroll
            for (int r = 0; r < 4; r++) acc[mf][nf][r] = 0.0f;

    const int NT = K / BK;

#define ISSUE_STAGE(s, kt) do { \
    uint32_t _da = aDst + (s) * STAGEF * 4; \
    uint32_t _db = bDst + (s) * STAGEF * 4; \
    const float* _pa = Ag + (kt) * BK; \
    const float* _pb = Bg + (kt) * BK; \
    _Pragma("unroll") \
    for (int _i = 0; _i < 4; _i++) { \
        asm volatile("cp.async.cg.shared.global [%0], [%1], 16;" \
                     :: "r"(_da + _i * 16), "l"(_pa + _i * 4)); \
        asm volatile("cp.async.cg.shared.global [%0], [%1], 16;" \
                     :: "r"(_db + _i * 16), "l"(_pb + _i * 4)); \
    } \
    asm volatile("cp.async.commit_group;"); \
} while (0)

    ISSUE_STAGE(0, 0);
    ISSUE_STAGE(1, 1);

    int stage = 0;
    for (int kt = 0; kt < NT; kt++) {
        if (kt == NT - 1) {
            asm volatile("cp.async.wait_group 0;");
        } else {
            asm volatile("cp.async.wait_group 1;");
        }
        __syncthreads();

        if (kt + 2 < NT) {
            int s2 = stage + 2; if (s2 >= NSTAGE) s2 -= NSTAGE;
            ISSUE_STAGE(s2, kt + 2);
        }

        const uint32_t aB = aBase0 + (uint32_t)stage * (STAGEF * 4);
        const uint32_t bB = bBase0 + (uint32_t)stage * (STAGEF * 4);

#pragma unroll
        for (int ks = 0; ks < 4; ks++) {
            uint32_t af[4][4];
#pragma unroll
            for (int mf = 0; mf < 4; mf++)
                ldm_x4(af[mf], aB + (uint32_t)(mf * 16 * BKP) * 4 + ks * 32);
            uint32_t bf[2][4];
#pragma unroll
            for (int np = 0; np < 2; np++)
                ldm_x4(bf[np], bB + (uint32_t)(np * 16 * BKP) * 4 + ks * 32);
#pragma unroll
            for (int mf = 0; mf < 4; mf++)
#pragma unroll
                for (int nf = 0; nf < 4; nf++)
                    mma_tf32(acc[mf][nf], af[mf], &bf[nf >> 1][(nf & 1) * 2]);
        }

        stage = stage + 1; if (stage >= NSTAGE) stage -= NSTAGE;
    }

    const int vmode = (vt != nullptr) && (n0 >= 2 * HID);
#pragma unroll
    for (int mf = 0; mf < 4; mf++) {
        const int row0 = m0 + wm * 64 + mf * 16 + g;
#pragma unroll
        for (int nf = 0; nf < 4; nf++) {
            const int col = n0 + wn * 32 + nf * 8 + 2 * tig;
            float b0 = 0.0f, b1 = 0.0f;
            if (bias) { b0 = bias[col]; b1 = bias[col + 1]; }
            float v00 = acc[mf][nf][0] + b0, v01 = acc[mf][nf][1] + b1;
            float v10 = acc[mf][nf][2] + b0, v11 = acc[mf][nf][3] + b1;
            if (round_out) {
                v00 = to_tf32(v00); v01 = to_tf32(v01);
                v10 = to_tf32(v10); v11 = to_tf32(v11);
            }
            if (vmode) {
                // V part: write transposed vt[(b*NH+h)*DH + d][s]
                const int vh = col - 2 * HID;
                const int bb = row0 >> 11;
                const int ss = row0 & 2047;
                float* vp = vt + ((size_t)(bb * NH) << 17) + (size_t)vh * S_LEN + ss;
                vp[0] = v00;
                vp[S_LEN] = v01;
                vp[8] = v10;
                vp[S_LEN + 8] = v11;
            } else {
                float2 w0 = {v00, v01};
                float2 w1 = {v10, v11};
                *(float2*)(C + (size_t)row0 * N + col) = w0;
                *(float2*)(C + (size_t)(row0 + 8) * N + col) = w1;
            }
        }
    }
}

// ---------------------------------------------------------------------------
// tf32 flash attention. CTA = 64 queries of one (b,h), 128 threads (4 warps).
// Q in registers; K & P fragments via ldmatrix; V pre-transposed in gmem so
// PV B-fragments are also ldmatrix. K/Vt double-buffered cp.async.
// ---------------------------------------------------------------------------
#define LDQ 68
#define LDVT 68
#define SM_P 0
#define SM_PSZ (64 * LDQ)
#define SM_K SM_PSZ
#define SM_KSZ (64 * LDQ)
#define SM_V (SM_K + 2 * SM_KSZ)
#define SM_VSZ (64 * LDVT)
#define SMEM_ATT ((SM_V + 2 * SM_VSZ) * 4)   // 87040 bytes

__global__ __launch_bounds__(128) void attn_tc_kernel(
    const float* __restrict__ qkv, const float* __restrict__ vtg,
    float* __restrict__ outp)
{
    extern __shared__ float sm[];
    const int tid = threadIdx.x;
    const int lane = tid & 31;
    const int wid = tid >> 5;
    const int g = lane >> 2;
    const int tig = lane & 3;
    const int ri = lane & 7;
    const int tq = lane >> 3;
    const int bh = blockIdx.y;
    const int b = bh >> 4;
    const int h = bh & 15;
    const int q0 = blockIdx.x * 64;

    const float* qbase = qkv + (size_t)b * S_LEN * 3 * HID + h * DH;
    const float* vbase = vtg + ((size_t)bh) * DH * S_LEN;

#define LOAD_KV(kt, buf) do { \
    _Pragma("unroll") \
    for (int _i = 0; _i < 8; _i++) { \
        int _t = tid + _i * 128; \
        int _r = _t >> 4, _c = (_t & 15) << 2; \
        const float* _sk = qbase + (size_t)((kt) * 64 + _r) * 3 * HID + HID + _c; \
        asm volatile("cp.async.cg.shared.global [%0], [%1], 16;" \
            :: "r"(smem_u32(sm + SM_K + (buf) * SM_KSZ + _r * LDQ + _c)), "l"(_sk)); \
        const float* _sv = vbase + (size_t)_r * S_LEN + (kt) * 64 + _c; \
        asm volatile("cp.async.cg.shared.global [%0], [%1], 16;" \
            :: "r"(smem_u32(sm + SM_V + (buf) * SM_VSZ + _r * LDVT + _c)), "l"(_sv)); \
    } \
} while (0)

    // stage Q into P buffer, then K0/V0, K1/V1
#pragma unroll
    for (int i = 0; i < 8; i++) {
        int t = tid + i * 128;
        int r = t >> 4, c = (t & 15) << 2;
        const float* sq = qbase + (size_t)(q0 + r) * 3 * HID + c;
        asm volatile("cp.async.cg.shared.global [%0], [%1], 16;"
            :: "r"(smem_u32(sm + SM_P + r * LDQ + c)), "l"(sq));
    }
    asm volatile("cp.async.commit_group;");
    LOAD_KV(0, 0);
    asm volatile("cp.async.commit_group;");
    LOAD_KV(1, 1);
    asm volatile("cp.async.commit_group;");

    float* Pw = sm + SM_P + (wid * 16) * LDQ;

    // ldmatrix lane offsets (bytes)
    const uint32_t aLane = (uint32_t)(((tq & 1) * 8 + ri) * LDQ) * 4 + (tq >> 1) * 16;
    const uint32_t bLaneK = (uint32_t)(((tq >> 1) * 8 + ri) * LDQ) * 4 + (tq & 1) * 16;
    const uint32_t bLaneV = (uint32_t)(((tq >> 1) * 8 + ri) * LDVT) * 4 + (tq & 1) * 16;
    const uint32_t pAddr = smem_u32(Pw) + aLane;

    // Q fragments -> registers
    asm volatile("cp.async.wait_group 2;");
    __syncthreads();
    uint32_t qf[8][4];
#pragma unroll
    for (int kf = 0; kf < 8; kf++) ldm_x4(qf[kf], pAddr + kf * 32);

    float m0 = -1e30f, m1 = -1e30f, l0 = 0.0f, l1 = 0.0f;
    float oacc[8][4];
#pragma unroll
    for (int nf = 0; nf < 8; nf++)
#pragma unroll
        for (int r = 0; r < 4; r++) oacc[nf][r] = 0.0f;

    for (int kt = 0; kt < S_LEN / 64; kt++) {
        asm volatile("cp.async.wait_group 1;");
        __syncthreads();
        const uint32_t kAddr =
            smem_u32(sm + SM_K + (kt & 1) * SM_KSZ) + bLaneK;
        const uint32_t vAddr =
            smem_u32(sm + SM_V + (kt & 1) * SM_VSZ) + bLaneV;

        // ---- S = Q K^T ----
        float sacc[8][4];
#pragma unroll
        for (int nf = 0; nf < 8; nf++)
#pragma unroll
            for (int r = 0; r < 4; r++) sacc[nf][r] = 0.0f;

#pragma unroll
        for (int kf = 0; kf < 8; kf++) {
#pragma unroll
            for (int np = 0; np < 4; np++) {
                uint32_t kfr[4];
                ldm_x4(kfr, kAddr + (uint32_t)(np * 16 * LDQ) * 4 + kf * 32);
                mma_tf32(sacc[2 * np], qf[kf], kfr);
                mma_tf32(sacc[2 * np + 1], qf[kf], kfr + 2);
            }
        }

        // ---- online softmax (rows g and g+8) ----
        float rmax0 = -1e30f, rmax1 = -1e30f;
#pragma unroll
        for (int nf = 0; nf < 8; nf++) {
#pragma unroll
            for (int r = 0; r < 4; r++) sacc[nf][r] *= SCALE_LOG2E;
            rmax0 = fmaxf(rmax0, fmaxf(sacc[nf][0], sacc[nf][1]));
            rmax1 = fmaxf(rmax1, fmaxf(sacc[nf][2], sacc[nf][3]));
        }
        rmax0 = fmaxf(rmax0, __shfl_xor_sync(0xffffffffu, rmax0, 1));
        rmax0 = fmaxf(rmax0, __shfl_xor_sync(0xffffffffu, rmax0, 2));
        rmax1 = fmaxf(rmax1, __shfl_xor_sync(0xffffffffu, rmax1, 1));
        rmax1 = fmaxf(rmax1, __shfl_xor_sync(0xffffffffu, rmax1, 2));

        const float mn0 = fmaxf(m0, rmax0);
        const float mn1 = fmaxf(m1, rmax1);
        const float corr0 = exp2_fast(m0 - mn0);
        const float corr1 = exp2_fast(m1 - mn1);
        m0 = mn0; m1 = mn1;

        float s0 = 0.0f, s1 = 0.0f;
        __syncwarp();
#pragma unroll
        for (int nf = 0; nf < 8; nf++) {
            float p0 = exp2_fast(sacc[nf][0] - mn0);
            float p1 = exp2_fast(sacc[nf][1] - mn0);
            float p2 = exp2_fast(sacc[nf][2] - mn1);
            float p3 = exp2_fast(sacc[nf][3] - mn1);
            s0 += p0 + p1;
            s1 += p2 + p3;
            float2 lo = {to_tf32(p0), to_tf32(p1)};
            float2 hi = {to_tf32(p2), to_tf32(p3)};
            *(float2*)(Pw + g * LDQ + nf * 8 + 2 * tig) = lo;
            *(float2*)(Pw + (g + 8) * LDQ + nf * 8 + 2 * tig) = hi;
        }
        s0 += __shfl_xor_sync(0xffffffffu, s0, 1);
        s0 += __shfl_xor_sync(0xffffffffu, s0, 2);
        s1 += __shfl_xor_sync(0xffffffffu, s1, 1);
        s1 += __shfl_xor_sync(0xffffffffu, s1, 2);
        l0 = l0 * corr0 + s0;
        l1 = l1 * corr1 + s1;
#pragma unroll
        for (int nf = 0; nf < 8; nf++) {
            oacc[nf][0] *= corr0; oacc[nf][1] *= corr0;
            oacc[nf][2] *= corr1; oacc[nf][3] *= corr1;
        }
        __syncwarp();

        // ---- O += P V  (B-frags from transposed V tile) ----
#pragma unroll
        for (int kf = 0; kf < 8; kf++) {
            uint32_t pf[4];
            ldm_x4(pf, pAddr + kf * 32);
#pragma unroll
            for (int np = 0; np < 4; np++) {
                uint32_t vfr[4];
                ldm_x4(vfr, vAddr + (uint32_t)(np * 16 * LDVT) * 4 + kf * 32);
                mma_tf32(oacc[2 * np], pf, vfr);
                mma_tf32(oacc[2 * np + 1], pf, vfr + 2);
            }
        }

        __syncthreads();
        if (kt + 2 < S_LEN / 64) LOAD_KV(kt + 2, kt & 1);
        asm volatile("cp.async.commit_group;");
    }

    // ---- epilogue (tf32-rounded for out-projection) ----
    const float inv0 = 1.0f / l0;
    const float inv1 = 1.0f / l1;
    const int row0 = q0 + wid * 16 + g;
    float* od = outp + (size_t)(b * S_LEN + row0) * HID + h * DH;
#pragma unroll
    for (int nf = 0; nf < 8; nf++) {
        const int col = nf * 8 + 2 * tig;
        float2 v0 = {to_tf32(oacc[nf][0] * inv0), to_tf32(oacc[nf][1] * inv0)};
        float2 v1 = {to_tf32(oacc[nf][2] * inv1), to_tf32(oacc[nf][3] * inv1)};
        *(float2*)(od + col) = v0;
        *(float2*)(od + (size_t)8 * HID + col) = v1;
    }
}

// ---------------------------------------------------------------------------
// Launch
// ---------------------------------------------------------------------------
extern "C" void kernel_launch(void* const* d_in, const int* in_sizes, int n_in,
                              void* d_out, int out_size)
{
    const float* x     = (const float*)d_in[0];
    const float* w_qkv = (const float*)d_in[1];
    const float* w_out = (const float*)d_in[2];
    const float* b_out = (const float*)d_in[3];
    float* out = (float*)d_out;

    float *qkv_p, *vt_p, *att_p, *xr_p, *wqkvr_p, *woutr_p;
    cudaGetSymbolAddress((void**)&qkv_p, g_qkv);
    cudaGetSymbolAddress((void**)&vt_p, g_vt);
    cudaGetSymbolAddress((void**)&att_p, g_att);
    cudaGetSymbolAddress((void**)&xr_p, g_xr);
    cudaGetSymbolAddress((void**)&wqkvr_p, g_wqkvr);
    cudaGetSymbolAddress((void**)&woutr_p, g_woutr);

    const int gemm_smem = NSTAGE * 2 * STAGEF * (int)sizeof(float);
    cudaFuncSetAttribute(gemm_mma_kernel,
                         cudaFuncAttributeMaxDynamicSharedMemorySize, gemm_smem);
    cudaFuncSetAttribute(attn_tc_kernel,
                         cudaFuncAttributeMaxDynamicSharedMemorySize, SMEM_ATT);

    // 0) tf32-round MMA inputs
    {
        int n1 = MTOT * HID;
        int n2 = 3 * HID * HID;
        int n3 = HID * HID;
        round_tf32_kernel<<<(n1 / 4 + 255) / 256, 256>>>(x, xr_p, n1);
        round_tf32_kernel<<<(n2 / 4 + 255) / 256, 256>>>(w_qkv, wqkvr_p, n2);
        round_tf32_kernel<<<(n3 / 4 + 255) / 256, 256>>>(w_out, woutr_p, n3);
    }

    // 1) qkv = x @ w_qkv^T  (q,k -> g_qkv; v -> g_vt transposed; all rounded)
    gemm_mma_kernel<<<dim3(3 * HID / BN, MTOT / BM), 256, gemm_smem>>>(
        xr_p, wqkvr_p, nullptr, qkv_p, vt_p, MTOT, 3 * HID, HID, 1);

    // 2) tf32 flash attention (ldmatrix everywhere)
    attn_tc_kernel<<<dim3(S_LEN / 64, BATCH * NH), 128, SMEM_ATT>>>(
        qkv_p, vt_p, att_p);

    // 3) out = att @ w_out^T + b_out  (final output, NOT rounded)
    gemm_mma_kernel<<<dim3(HID / BN, MTOT / BM), 256, gemm_smem>>>(
        att_p, woutr_p, b_out, out, nullptr, MTOT, HID, HID, 0);
}

// round 9
// speedup vs baseline: 4.6732x; 1.7611x over previous
#include <cuda_runtime.h>
#include <cuda_fp16.h>
#include <math.h>
#include <stdint.h>

// Problem constants
#define BATCH 2
#define S_LEN 2048
#define HID   1024
#define NH    16
#define DH    64
#define MTOT (BATCH * S_LEN)   // 4096
#define SCALE_LOG2E 0.18033688011112042f  // 0.125 * log2(e)

// Scratch (allocation-free rule: __device__ globals)
__device__ __half g_qkv_h[(size_t)MTOT * 3 * HID];            // q,k used; v region unused
__device__ __half g_vt_h[(size_t)BATCH * NH * DH * S_LEN];    // V^T [b,h,d,s]
__device__ __half g_att_h[(size_t)MTOT * HID];                // attention out (fp16)
__device__ __half g_x_h[(size_t)MTOT * HID];                  // fp16 x
__device__ __half g_wqkv_h[(size_t)3 * HID * HID];            // fp16 w_qkv
__device__ __half g_wout_h[(size_t)HID * HID];                // fp16 w_out

__device__ __forceinline__ uint32_t smem_u32(const void* p) {
    uint32_t a;
    asm("{ .reg .u64 t; cvta.to.shared.u64 t, %1; cvt.u32.u64 %0, t; }"
        : "=r"(a) : "l"(p));
    return a;
}

// exp2 via FMA-pipe polynomial (no MUFU).
__device__ __forceinline__ float exp2_fast(float x) {
    x = fmaxf(x, -126.0f);
    float z = x + 12582912.0f;
    int ei = __float_as_int(z) - 0x4B400000;
    float f = x - (float)ei;
    float p = 1.3333558146e-3f;
    p = fmaf(p, f, 9.6181291057e-3f);
    p = fmaf(p, f, 5.5504108664e-2f);
    p = fmaf(p, f, 2.4022650695e-1f);
    p = fmaf(p, f, 6.9314718056e-1f);
    p = fmaf(p, f, 1.0f);
    return p * __int_as_float((ei + 127) << 23);
}

__device__ __forceinline__ void mma_f16(float* c, const uint32_t* a,
                                        const uint32_t* b) {
    asm volatile(
        "mma.sync.aligned.m16n8k16.row.col.f32.f16.f16.f32 "
        "{%0,%1,%2,%3}, {%4,%5,%6,%7}, {%8,%9}, {%0,%1,%2,%3};"
        : "+f"(c[0]), "+f"(c[1]), "+f"(c[2]), "+f"(c[3])
        : "r"(a[0]), "r"(a[1]), "r"(a[2]), "r"(a[3]), "r"(b[0]), "r"(b[1]));
}
__device__ __forceinline__ void ldm_x4(uint32_t* r, uint32_t addr) {
    asm volatile(
        "ldmatrix.sync.aligned.m8n8.x4.shared.b16 {%0,%1,%2,%3}, [%4];"
        : "=r"(r[0]), "=r"(r[1]), "=r"(r[2]), "=r"(r[3]) : "r"(addr));
}

// ---------------------------------------------------------------------------
// fp16 conversion prepass
// ---------------------------------------------------------------------------
__global__ __launch_bounds__(256) void to_half_kernel(
    const float* __restrict__ src, __half* __restrict__ dst, int n)
{
    int i = (blockIdx.x * blockDim.x + threadIdx.x) * 4;
    if (i < n) {
        float4 v = *(const float4*)(src + i);
        __half2 h0 = __floats2half2_rn(v.x, v.y);
        __half2 h1 = __floats2half2_rn(v.z, v.w);
        *(__half2*)(dst + i) = h0;
        *(__half2*)(dst + i + 2) = h1;
    }
}

// ---------------------------------------------------------------------------
// fp16 mma.sync GEMM: C[M,N] = A[M,K]*B[N,K]^T. CTA 128x128, BK=64 halves,
// 256 threads, 8 warps, warp tile 64x32 via m16n8k16. 3-stage cp.async.
// mode 0: C = float* out, +bias.  mode 1: half out; cols>=2048 -> vt.
// ---------------------------------------------------------------------------
#define BM 128
#define BN 128
#define BKH 64            // halves per k-tile
#define BKP 72            // padded stride (halves), 144 bytes
#define NSTAGE 3
#define STAGEH (BM * BKP) // halves per operand stage
#define STAGEB (STAGEH * 2)

__global__ __launch_bounds__(256) void gemm_h_kernel(
    const __half* __restrict__ A, const __half* __restrict__ B,
    const float* __restrict__ bias, float* __restrict__ Cf,
    __half* __restrict__ Ch, __half* __restrict__ vt,
    int M, int N, int K, int mode)
{
    extern __shared__ __half smh[];
    __half* As = smh;
    __half* Bs = smh + NSTAGE * STAGEH;

    const int tid = threadIdx.x;
    const int wid = tid >> 5;
    const int lane = tid & 31;
    const int g = lane >> 2;
    const int tig = lane & 3;
    const int ri = lane & 7;
    const int tq = lane >> 3;
    const int wm = wid & 1;
    const int wn = wid >> 1;
    const int m0 = blockIdx.y * BM;
    const int n0 = blockIdx.x * BN;

    // loader: thread owns one row of A (tid<128) or B (tid>=128); 8 x 16B
    const int lrow = tid & 127;
    const int isB = tid >> 7;
    const __half* Rg = (isB ? B + (size_t)(n0 + lrow) * K
                            : A + (size_t)(m0 + lrow) * K);
    const uint32_t rDst = smem_u32((isB ? Bs : As) + lrow * BKP);

    // ldmatrix lane offsets (bytes); row stride 144B
    const uint32_t aLane = (uint32_t)(((tq & 1) * 8 + ri) * 144) + (tq >> 1) * 16;
    const uint32_t bLane = (uint32_t)(((tq >> 1) * 8 + ri) * 144) + (tq & 1) * 16;
    const uint32_t aBase0 = smem_u32(As) + (uint32_t)(wm * 64 * 144) + aLane;
    const uint32_t bBase0 = smem_u32(Bs) + (uint32_t)(wn * 32 * 144) + bLane;

    float acc[4][4][4];
#pragma unroll
    for (int mf = 0; mf < 4; mf++)
#pragma unroll
        for (int nf = 0; nf < 4; nf++)
#pragma unroll
            for (int r = 0; r < 4; r++) acc[mf][nf][r] = 0.0f;

    const int NT = K / BKH;

#define ISSUE_STAGE(s, kt) do { \
    uint32_t _d = rDst + (s) * (STAGEH * 2); \
    const __half* _p = Rg + (kt) * BKH; \
    _Pragma("unroll") \
    for (int _i = 0; _i < 8; _i++) { \
        asm volatile("cp.async.cg.shared.global [%0], [%1], 16;" \
                     :: "r"(_d + _i * 16), "l"(_p + _i * 8)); \
    } \
    asm volatile("cp.async.commit_group;"); \
} while (0)

    ISSUE_STAGE(0, 0);
    ISSUE_STAGE(1, 1);

    int stage = 0;
    for (int kt = 0; kt < NT; kt++) {
        if (kt == NT - 1) {
            asm volatile("cp.async.wait_group 0;");
        } else {
            asm volatile("cp.async.wait_group 1;");
        }
        __syncthreads();

        if (kt + 2 < NT) {
            int s2 = stage + 2; if (s2 >= NSTAGE) s2 -= NSTAGE;
            ISSUE_STAGE(s2, kt + 2);
        }

        const uint32_t aB = aBase0 + (uint32_t)stage * (STAGEH * 2);
        const uint32_t bB = bBase0 + (uint32_t)stage * (STAGEH * 2);

#pragma unroll
        for (int ks = 0; ks < 4; ks++) {   // 4 x k16
            uint32_t af[4][4];
#pragma unroll
            for (int mf = 0; mf < 4; mf++)
                ldm_x4(af[mf], aB + (uint32_t)(mf * 16 * 144) + ks * 32);
            uint32_t bf[2][4];
#pragma unroll
            for (int np = 0; np < 2; np++)
                ldm_x4(bf[np], bB + (uint32_t)(np * 16 * 144) + ks * 32);
#pragma unroll
            for (int mf = 0; mf < 4; mf++)
#pragma unroll
                for (int nf = 0; nf < 4; nf++)
                    mma_f16(acc[mf][nf], af[mf], &bf[nf >> 1][(nf & 1) * 2]);
        }

        stage = stage + 1; if (stage >= NSTAGE) stage -= NSTAGE;
    }

#pragma unroll
    for (int mf = 0; mf < 4; mf++) {
        const int row0 = m0 + wm * 64 + mf * 16 + g;
#pragma unroll
        for (int nf = 0; nf < 4; nf++) {
            const int col = n0 + wn * 32 + nf * 8 + 2 * tig;
            float v00 = acc[mf][nf][0], v01 = acc[mf][nf][1];
            float v10 = acc[mf][nf][2], v11 = acc[mf][nf][3];
            if (mode == 0) {
                float b0 = bias ? bias[col] : 0.0f;
                float b1 = bias ? bias[col + 1] : 0.0f;
                float2 w0 = {v00 + b0, v01 + b1};
                float2 w1 = {v10 + b0, v11 + b1};
                *(float2*)(Cf + (size_t)row0 * N + col) = w0;
                *(float2*)(Cf + (size_t)(row0 + 8) * N + col) = w1;
            } else if (col < 2 * HID) {
                *(__half2*)(Ch + (size_t)row0 * N + col) =
                    __floats2half2_rn(v00, v01);
                *(__half2*)(Ch + (size_t)(row0 + 8) * N + col) =
                    __floats2half2_rn(v10, v11);
            } else {
                const int vh = col - 2 * HID;
                const int bb = row0 >> 11;
                const int ss = row0 & 2047;
                __half* vp = vt + ((size_t)(bb * NH) << 17) +
                             (size_t)vh * S_LEN + ss;
                vp[0] = __float2half_rn(v00);
                vp[S_LEN] = __float2half_rn(v01);
                vp[8] = __float2half_rn(v10);
                vp[S_LEN + 8] = __float2half_rn(v11);
            }
        }
    }
}

// ---------------------------------------------------------------------------
// fp16 flash attention. CTA = 64 queries of one (b,h), 128 threads (4 warps).
// Q in regs; K/P/Vt fragments via ldmatrix b16; m16n8k16 MMAs, fp32 softmax.
// smem ~45KB -> 4 CTAs/SM.
// ---------------------------------------------------------------------------
#define LDH 72     // halves stride (144 B)
#define SM_P 0
#define SM_PSZ (64 * LDH)
#define SM_K SM_PSZ
#define SM_KSZ (64 * LDH)
#define SM_V (SM_K + 2 * SM_KSZ)
#define SM_VSZ (64 * LDH)
#define SMEM_ATT ((SM_V + 2 * SM_VSZ) * 2)   // 46080 bytes

__global__ __launch_bounds__(128) void attn_h_kernel(
    const __half* __restrict__ qkv, const __half* __restrict__ vtg,
    __half* __restrict__ outp)
{
    extern __shared__ __half smh[];
    const int tid = threadIdx.x;
    const int lane = tid & 31;
    const int wid = tid >> 5;
    const int g = lane >> 2;
    const int tig = lane & 3;
    const int ri = lane & 7;
    const int tq = lane >> 3;
    const int bh = blockIdx.y;
    const int b = bh >> 4;
    const int h = bh & 15;
    const int q0 = blockIdx.x * 64;

    const __half* qbase = qkv + (size_t)b * S_LEN * 3 * HID + h * DH;
    const __half* vbase = vtg + ((size_t)bh) * DH * S_LEN;

    // K tile row r: 64 halves = 8 x 16B chunks; 64 rows -> 512 chunks; 4/thread
#define LOAD_KV(kt, buf) do { \
    _Pragma("unroll") \
    for (int _i = 0; _i < 4; _i++) { \
        int _t = tid + _i * 128; \
        int _r = _t >> 3, _c = (_t & 7) * 8; \
        const __half* _sk = qbase + (size_t)((kt) * 64 + _r) * 3 * HID + HID + _c; \
        asm volatile("cp.async.cg.shared.global [%0], [%1], 16;" \
            :: "r"(smem_u32(smh + SM_K + (buf) * SM_KSZ + _r * LDH + _c)), "l"(_sk)); \
        const __half* _sv = vbase + (size_t)_r * S_LEN + (kt) * 64 + _c; \
        asm volatile("cp.async.cg.shared.global [%0], [%1], 16;" \
            :: "r"(smem_u32(smh + SM_V + (buf) * SM_VSZ + _r * LDH + _c)), "l"(_sv)); \
    } \
} while (0)

    // stage Q via P buffer, then K0/V0, K1/V1
#pragma unroll
    for (int i = 0; i < 4; i++) {
        int t = tid + i * 128;
        int r = t >> 3, c = (t & 7) * 8;
        const __half* sq = qbase + (size_t)(q0 + r) * 3 * HID + c;
        asm volatile("cp.async.cg.shared.global [%0], [%1], 16;"
            :: "r"(smem_u32(smh + SM_P + r * LDH + c)), "l"(sq));
    }
    asm volatile("cp.async.commit_group;");
    LOAD_KV(0, 0);
    asm volatile("cp.async.commit_group;");
    LOAD_KV(1, 1);
    asm volatile("cp.async.commit_group;");

    __half* Pw = smh + SM_P + (wid * 16) * LDH;

    const uint32_t aLane = (uint32_t)(((tq & 1) * 8 + ri) * 144) + (tq >> 1) * 16;
    const uint32_t bLane = (uint32_t)(((tq >> 1) * 8 + ri) * 144) + (tq & 1) * 16;
    const uint32_t pAddr = smem_u32(Pw) + aLane;

    // Q fragments -> registers (4 x k16)
    asm volatile("cp.async.wait_group 2;");
    __syncthreads();
    uint32_t qf[4][4];
#pragma unroll
    for (int ks = 0; ks < 4; ks++) ldm_x4(qf[ks], pAddr + ks * 32);

    float m0 = -1e30f, m1 = -1e30f, l0 = 0.0f, l1 = 0.0f;
    float oacc[8][4];
#pragma unroll
    for (int nf = 0; nf < 8; nf++)
#pragma unroll
        for (int r = 0; r < 4; r++) oacc[nf][r] = 0.0f;

    for (int kt = 0; kt < S_LEN / 64; kt++) {
        asm volatile("cp.async.wait_group 1;");
        __syncthreads();
        const uint32_t kAddr =
            smem_u32(smh + SM_K + (kt & 1) * SM_KSZ) + bLane;
        const uint32_t vAddr =
            smem_u32(smh + SM_V + (kt & 1) * SM_VSZ) + bLane;

        // ---- S = Q K^T ----
        float sacc[8][4];
#pragma unroll
        for (int nf = 0; nf < 8; nf++)
#pragma unroll
            for (int r = 0; r < 4; r++) sacc[nf][r] = 0.0f;

#pragma unroll
        for (int ks = 0; ks < 4; ks++) {
#pragma unroll
            for (int np = 0; np < 4; np++) {
                uint32_t kfr[4];
                ldm_x4(kfr, kAddr + (uint32_t)(np * 16 * 144) + ks * 32);
                mma_f16(sacc[2 * np], qf[ks], kfr);
                mma_f16(sacc[2 * np + 1], qf[ks], kfr + 2);
            }
        }

        // ---- online softmax (rows g, g+8) ----
        float rmax0 = -1e30f, rmax1 = -1e30f;
#pragma unroll
        for (int nf = 0; nf < 8; nf++) {
#pragma unroll
            for (int r = 0; r < 4; r++) sacc[nf][r] *= SCALE_LOG2E;
            rmax0 = fmaxf(rmax0, fmaxf(sacc[nf][0], sacc[nf][1]));
            rmax1 = fmaxf(rmax1, fmaxf(sacc[nf][2], sacc[nf][3]));
        }
        rmax0 = fmaxf(rmax0, __shfl_xor_sync(0xffffffffu, rmax0, 1));
        rmax0 = fmaxf(rmax0, __shfl_xor_sync(0xffffffffu, rmax0, 2));
        rmax1 = fmaxf(rmax1, __shfl_xor_sync(0xffffffffu, rmax1, 1));
        rmax1 = fmaxf(rmax1, __shfl_xor_sync(0xffffffffu, rmax1, 2));

        const float mn0 = fmaxf(m0, rmax0);
        const float mn1 = fmaxf(m1, rmax1);
        const float corr0 = exp2_fast(m0 - mn0);
        const float corr1 = exp2_fast(m1 - mn1);
        m0 = mn0; m1 = mn1;

        float s0 = 0.0f, s1 = 0.0f;
        __syncwarp();
#pragma unroll
        for (int nf = 0; nf < 8; nf++) {
            float p0 = exp2_fast(sacc[nf][0] - mn0);
            float p1 = exp2_fast(sacc[nf][1] - mn0);
            float p2 = exp2_fast(sacc[nf][2] - mn1);
            float p3 = exp2_fast(sacc[nf][3] - mn1);
            s0 += p0 + p1;
            s1 += p2 + p3;
            *(__half2*)(Pw + g * LDH + nf * 8 + 2 * tig) =
                __floats2half2_rn(p0, p1);
            *(__half2*)(Pw + (g + 8) * LDH + nf * 8 + 2 * tig) =
                __floats2half2_rn(p2, p3);
        }
        s0 += __shfl_xor_sync(0xffffffffu, s0, 1);
        s0 += __shfl_xor_sync(0xffffffffu, s0, 2);
        s1 += __shfl_xor_sync(0xffffffffu, s1, 1);
        s1 += __shfl_xor_sync(0xffffffffu, s1, 2);
        l0 = l0 * corr0 + s0;
        l1 = l1 * corr1 + s1;
#pragma unroll
        for (int nf = 0; nf < 8; nf++) {
            oacc[nf][0] *= corr0; oacc[nf][1] *= corr0;
            oacc[nf][2] *= corr1; oacc[nf][3] *= corr1;
        }
        __syncwarp();

        // ---- O += P V (Vt tiles) ----
#pragma unroll
        for (int ks = 0; ks < 4; ks++) {
            uint32_t pf[4];
            ldm_x4(pf, pAddr + ks * 32);
#pragma unroll
            for (int np = 0; np < 4; np++) {
                uint32_t vfr[4];
                ldm_x4(vfr, vAddr + (uint32_t)(np * 16 * 144) + ks * 32);
                mma_f16(oacc[2 * np], pf, vfr);
                mma_f16(oacc[2 * np + 1], pf, vfr + 2);
            }
        }

        __syncthreads();
        if (kt + 2 < S_LEN / 64) LOAD_KV(kt + 2, kt & 1);
        asm volatile("cp.async.commit_group;");
    }

    // ---- epilogue: fp16 out for the out-projection ----
    const float inv0 = 1.0f / l0;
    const float inv1 = 1.0f / l1;
    const int row0 = q0 + wid * 16 + g;
    __half* od = outp + (size_t)(b * S_LEN + row0) * HID + h * DH;
#pragma unroll
    for (int nf = 0; nf < 8; nf++) {
        const int col = nf * 8 + 2 * tig;
        *(__half2*)(od + col) =
            __floats2half2_rn(oacc[nf][0] * inv0, oacc[nf][1] * inv0);
        *(__half2*)(od + (size_t)8 * HID + col) =
            __floats2half2_rn(oacc[nf][2] * inv1, oacc[nf][3] * inv1);
    }
}

// ---------------------------------------------------------------------------
// Launch
// ---------------------------------------------------------------------------
extern "C" void kernel_launch(void* const* d_in, const int* in_sizes, int n_in,
                              void* d_out, int out_size)
{
    const float* x     = (const float*)d_in[0];
    const float* w_qkv = (const float*)d_in[1];
    const float* w_out = (const float*)d_in[2];
    const float* b_out = (const float*)d_in[3];
    float* out = (float*)d_out;

    __half *qkv_p, *vt_p, *att_p, *x_p, *wqkv_p, *wout_p;
    cudaGetSymbolAddress((void**)&qkv_p, g_qkv_h);
    cudaGetSymbolAddress((void**)&vt_p, g_vt_h);
    cudaGetSymbolAddress((void**)&att_p, g_att_h);
    cudaGetSymbolAddress((void**)&x_p, g_x_h);
    cudaGetSymbolAddress((void**)&wqkv_p, g_wqkv_h);
    cudaGetSymbolAddress((void**)&wout_p, g_wout_h);

    const int gemm_smem = NSTAGE * 2 * STAGEH * 2;  // 110592 bytes
    cudaFuncSetAttribute(gemm_h_kernel,
                         cudaFuncAttributeMaxDynamicSharedMemorySize, gemm_smem);
    cudaFuncSetAttribute(attn_h_kernel,
                         cudaFuncAttributeMaxDynamicSharedMemorySize, SMEM_ATT);

    // 0) fp32 -> fp16 (rn) inputs
    {
        int n1 = MTOT * HID;
        int n2 = 3 * HID * HID;
        int n3 = HID * HID;
        to_half_kernel<<<(n1 / 4 + 255) / 256, 256>>>(x, x_p, n1);
        to_half_kernel<<<(n2 / 4 + 255) / 256, 256>>>(w_qkv, wqkv_p, n2);
        to_half_kernel<<<(n3 / 4 + 255) / 256, 256>>>(w_out, wout_p, n3);
    }

    // 1) qkv = x @ w_qkv^T  (q,k -> g_qkv_h; v -> g_vt_h transposed)
    gemm_h_kernel<<<dim3(3 * HID / BN, MTOT / BM), 256, gemm_smem>>>(
        x_p, wqkv_p, nullptr, nullptr, qkv_p, vt_p, MTOT, 3 * HID, HID, 1);

    // 2) fp16 flash attention
    attn_h_kernel<<<dim3(S_LEN / 64, BATCH * NH), 128, SMEM_ATT>>>(
        qkv_p, vt_p, att_p);

    // 3) out = att @ w_out^T + b_out  (fp32 output)
    gemm_h_kernel<<<dim3(HID / BN, MTOT / BM), 256, gemm_smem>>>(
        att_p, wout_p, b_out, out, nullptr, nullptr, MTOT, HID, HID, 0);
}

// round 10
// speedup vs baseline: 5.0273x; 1.0758x over previous
#include <cuda_runtime.h>
#include <cuda_fp16.h>
#include <math.h>
#include <stdint.h>

// Problem constants
#define BATCH 2
#define S_LEN 2048
#define HID   1024
#define NH    16
#define DH    64
#define MTOT (BATCH * S_LEN)   // 4096
#define SCALE_LOG2E 0.18033688011112042f  // 0.125 * log2(e)

// Scratch (allocation-free rule: __device__ globals)
__device__ __half g_qkv_h[(size_t)MTOT * 3 * HID];
__device__ __half g_vt_h[(size_t)BATCH * NH * DH * S_LEN];    // V^T [b,h,d,s]
__device__ __half g_att_h[(size_t)MTOT * HID];
__device__ __half g_x_h[(size_t)MTOT * HID];
__device__ __half g_wqkv_h[(size_t)3 * HID * HID];
__device__ __half g_wout_h[(size_t)HID * HID];

__device__ __forceinline__ uint32_t smem_u32(const void* p) {
    uint32_t a;
    asm("{ .reg .u64 t; cvta.to.shared.u64 t, %1; cvt.u32.u64 %0, t; }"
        : "=r"(a) : "l"(p));
    return a;
}

// exp2 via FMA-pipe polynomial (no MUFU).
__device__ __forceinline__ float exp2_fast(float x) {
    x = fmaxf(x, -126.0f);
    float z = x + 12582912.0f;
    int ei = __float_as_int(z) - 0x4B400000;
    float f = x - (float)ei;
    float p = 1.3333558146e-3f;
    p = fmaf(p, f, 9.6181291057e-3f);
    p = fmaf(p, f, 5.5504108664e-2f);
    p = fmaf(p, f, 2.4022650695e-1f);
    p = fmaf(p, f, 6.9314718056e-1f);
    p = fmaf(p, f, 1.0f);
    return p * __int_as_float((ei + 127) << 23);
}

__device__ __forceinline__ void mma_f16(float* c, const uint32_t* a,
                                        const uint32_t* b) {
    asm volatile(
        "mma.sync.aligned.m16n8k16.row.col.f32.f16.f16.f32 "
        "{%0,%1,%2,%3}, {%4,%5,%6,%7}, {%8,%9}, {%0,%1,%2,%3};"
        : "+f"(c[0]), "+f"(c[1]), "+f"(c[2]), "+f"(c[3])
        : "r"(a[0]), "r"(a[1]), "r"(a[2]), "r"(a[3]), "r"(b[0]), "r"(b[1]));
}
__device__ __forceinline__ void ldm_x4(uint32_t* r, uint32_t addr) {
    asm volatile(
        "ldmatrix.sync.aligned.m8n8.x4.shared.b16 {%0,%1,%2,%3}, [%4];"
        : "=r"(r[0]), "=r"(r[1]), "=r"(r[2]), "=r"(r[3]) : "r"(addr));
}

// ---------------------------------------------------------------------------
// fp16 conversion prepass
// ---------------------------------------------------------------------------
__global__ __launch_bounds__(256) void to_half_kernel(
    const float* __restrict__ src, __half* __restrict__ dst, int n)
{
    int i = (blockIdx.x * blockDim.x + threadIdx.x) * 4;
    if (i < n) {
        float4 v = *(const float4*)(src + i);
        *(__half2*)(dst + i) = __floats2half2_rn(v.x, v.y);
        *(__half2*)(dst + i + 2) = __floats2half2_rn(v.z, v.w);
    }
}

// ---------------------------------------------------------------------------
// fp16 mma.sync GEMM with software-pipelined fragment loads.
// CTA 128x128, BK=64 halves, 256 threads, warp tile 64x32, 3-stage cp.async.
// ---------------------------------------------------------------------------
#define BM 128
#define BN 128
#define BKH 64
#define BKP 72
#define NSTAGE 3
#define STAGEH (BM * BKP)

__global__ __launch_bounds__(256, 2) void gemm_h_kernel(
    const __half* __restrict__ A, const __half* __restrict__ B,
    const float* __restrict__ bias, float* __restrict__ Cf,
    __half* __restrict__ Ch, __half* __restrict__ vt,
    int M, int N, int K, int mode)
{
    extern __shared__ __half smh[];
    __half* As = smh;
    __half* Bs = smh + NSTAGE * STAGEH;

    const int tid = threadIdx.x;
    const int wid = tid >> 5;
    const int lane = tid & 31;
    const int g = lane >> 2;
    const int tig = lane & 3;
    const int ri = lane & 7;
    const int tq = lane >> 3;
    const int wm = wid & 1;
    const int wn = wid >> 1;
    const int m0 = blockIdx.y * BM;
    const int n0 = blockIdx.x * BN;

    const int lrow = tid & 127;
    const int isB = tid >> 7;
    const __half* Rg = (isB ? B + (size_t)(n0 + lrow) * K
                            : A + (size_t)(m0 + lrow) * K);
    const uint32_t rDst = smem_u32((isB ? Bs : As) + lrow * BKP);

    const uint32_t aLane = (uint32_t)(((tq & 1) * 8 + ri) * 144) + (tq >> 1) * 16;
    const uint32_t bLane = (uint32_t)(((tq >> 1) * 8 + ri) * 144) + (tq & 1) * 16;
    const uint32_t aBase0 = smem_u32(As) + (uint32_t)(wm * 64 * 144) + aLane;
    const uint32_t bBase0 = smem_u32(Bs) + (uint32_t)(wn * 32 * 144) + bLane;

    float acc[4][4][4];
#pragma unroll
    for (int mf = 0; mf < 4; mf++)
#pragma unroll
        for (int nf = 0; nf < 4; nf++)
#pragma unroll
            for (int r = 0; r < 4; r++) acc[mf][nf][r] = 0.0f;

    const int NT = K / BKH;

#define ISSUE_STAGE(s, kt) do { \
    uint32_t _d = rDst + (s) * (STAGEH * 2); \
    const __half* _p = Rg + (kt) * BKH; \
    _Pragma("unroll") \
    for (int _i = 0; _i < 8; _i++) { \
        asm volatile("cp.async.cg.shared.global [%0], [%1], 16;" \
                     :: "r"(_d + _i * 16), "l"(_p + _i * 8)); \
    } \
    asm volatile("cp.async.commit_group;"); \
} while (0)

#define LOAD_FRAGS(buf, aB, bB, ks) do { \
    _Pragma("unroll") \
    for (int _mf = 0; _mf < 4; _mf++) \
        ldm_x4(af[buf][_mf], (aB) + (uint32_t)(_mf * 16 * 144) + (ks) * 32); \
    _Pragma("unroll") \
    for (int _np = 0; _np < 2; _np++) \
        ldm_x4(bf[buf][_np], (bB) + (uint32_t)(_np * 16 * 144) + (ks) * 32); \
} while (0)

    ISSUE_STAGE(0, 0);
    ISSUE_STAGE(1, 1);

    uint32_t af[2][4][4];
    uint32_t bf[2][2][4];

    int stage = 0;
    for (int kt = 0; kt < NT; kt++) {
        if (kt == NT - 1) {
            asm volatile("cp.async.wait_group 0;");
        } else {
            asm volatile("cp.async.wait_group 1;");
        }
        __syncthreads();

        if (kt + 2 < NT) {
            int s2 = stage + 2; if (s2 >= NSTAGE) s2 -= NSTAGE;
            ISSUE_STAGE(s2, kt + 2);
        }

        const uint32_t aB = aBase0 + (uint32_t)stage * (STAGEH * 2);
        const uint32_t bB = bBase0 + (uint32_t)stage * (STAGEH * 2);

        LOAD_FRAGS(0, aB, bB, 0);
#pragma unroll
        for (int ks = 0; ks < 4; ks++) {
            const int cur = ks & 1;
            if (ks < 3) LOAD_FRAGS(cur ^ 1, aB, bB, ks + 1);
#pragma unroll
            for (int mf = 0; mf < 4; mf++)
#pragma unroll
                for (int nf = 0; nf < 4; nf++)
                    mma_f16(acc[mf][nf], af[cur][mf],
                            &bf[cur][nf >> 1][(nf & 1) * 2]);
        }

        stage = stage + 1; if (stage >= NSTAGE) stage -= NSTAGE;
    }

#pragma unroll
    for (int mf = 0; mf < 4; mf++) {
        const int row0 = m0 + wm * 64 + mf * 16 + g;
#pragma unroll
        for (int nf = 0; nf < 4; nf++) {
            const int col = n0 + wn * 32 + nf * 8 + 2 * tig;
            float v00 = acc[mf][nf][0], v01 = acc[mf][nf][1];
            float v10 = acc[mf][nf][2], v11 = acc[mf][nf][3];
            if (mode == 0) {
                float b0 = bias ? bias[col] : 0.0f;
                float b1 = bias ? bias[col + 1] : 0.0f;
                float2 w0 = {v00 + b0, v01 + b1};
                float2 w1 = {v10 + b0, v11 + b1};
                *(float2*)(Cf + (size_t)row0 * N + col) = w0;
                *(float2*)(Cf + (size_t)(row0 + 8) * N + col) = w1;
            } else if (col < 2 * HID) {
                *(__half2*)(Ch + (size_t)row0 * N + col) =
                    __floats2half2_rn(v00, v01);
                *(__half2*)(Ch + (size_t)(row0 + 8) * N + col) =
                    __floats2half2_rn(v10, v11);
            } else {
                const int vh = col - 2 * HID;
                const int bb = row0 >> 11;
                const int ss = row0 & 2047;
                __half* vp = vt + ((size_t)(bb * NH) << 17) +
                             (size_t)vh * S_LEN + ss;
                vp[0] = __float2half_rn(v00);
                vp[S_LEN] = __float2half_rn(v01);
                vp[8] = __float2half_rn(v10);
                vp[S_LEN + 8] = __float2half_rn(v11);
            }
        }
    }
}

// ---------------------------------------------------------------------------
// fp16 flash attention with pipelined fragment loads.
// CTA = 64 queries of one (b,h), 128 threads (4 warps), 4 CTAs/SM.
// ---------------------------------------------------------------------------
#define LDH 72
#define SM_P 0
#define SM_PSZ (64 * LDH)
#define SM_K SM_PSZ
#define SM_KSZ (64 * LDH)
#define SM_V (SM_K + 2 * SM_KSZ)
#define SM_VSZ (64 * LDH)
#define SMEM_ATT ((SM_V + 2 * SM_VSZ) * 2)   // 46080 bytes

__global__ __launch_bounds__(128, 4) void attn_h_kernel(
    const __half* __restrict__ qkv, const __half* __restrict__ vtg,
    __half* __restrict__ outp)
{
    extern __shared__ __half smh[];
    const int tid = threadIdx.x;
    const int lane = tid & 31;
    const int wid = tid >> 5;
    const int g = lane >> 2;
    const int tig = lane & 3;
    const int ri = lane & 7;
    const int tq = lane >> 3;
    const int bh = blockIdx.y;
    const int b = bh >> 4;
    const int h = bh & 15;
    const int q0 = blockIdx.x * 64;

    const __half* qbase = qkv + (size_t)b * S_LEN * 3 * HID + h * DH;
    const __half* vbase = vtg + ((size_t)bh) * DH * S_LEN;

#define LOAD_KV(kt, buf) do { \
    _Pragma("unroll") \
    for (int _i = 0; _i < 4; _i++) { \
        int _t = tid + _i * 128; \
        int _r = _t >> 3, _c = (_t & 7) * 8; \
        const __half* _sk = qbase + (size_t)((kt) * 64 + _r) * 3 * HID + HID + _c; \
        asm volatile("cp.async.cg.shared.global [%0], [%1], 16;" \
            :: "r"(smem_u32(smh + SM_K + (buf) * SM_KSZ + _r * LDH + _c)), "l"(_sk)); \
        const __half* _sv = vbase + (size_t)_r * S_LEN + (kt) * 64 + _c; \
        asm volatile("cp.async.cg.shared.global [%0], [%1], 16;" \
            :: "r"(smem_u32(smh + SM_V + (buf) * SM_VSZ + _r * LDH + _c)), "l"(_sv)); \
    } \
} while (0)

#pragma unroll
    for (int i = 0; i < 4; i++) {
        int t = tid + i * 128;
        int r = t >> 3, c = (t & 7) * 8;
        const __half* sq = qbase + (size_t)(q0 + r) * 3 * HID + c;
        asm volatile("cp.async.cg.shared.global [%0], [%1], 16;"
            :: "r"(smem_u32(smh + SM_P + r * LDH + c)), "l"(sq));
    }
    asm volatile("cp.async.commit_group;");
    LOAD_KV(0, 0);
    asm volatile("cp.async.commit_group;");
    LOAD_KV(1, 1);
    asm volatile("cp.async.commit_group;");

    __half* Pw = smh + SM_P + (wid * 16) * LDH;

    const uint32_t aLane = (uint32_t)(((tq & 1) * 8 + ri) * 144) + (tq >> 1) * 16;
    const uint32_t bLane = (uint32_t)(((tq >> 1) * 8 + ri) * 144) + (tq & 1) * 16;
    const uint32_t pAddr = smem_u32(Pw) + aLane;

    asm volatile("cp.async.wait_group 2;");
    __syncthreads();
    uint32_t qf[4][4];
#pragma unroll
    for (int ks = 0; ks < 4; ks++) ldm_x4(qf[ks], pAddr + ks * 32);

    float m0 = -1e30f, m1 = -1e30f, l0 = 0.0f, l1 = 0.0f;
    float oacc[8][4];
#pragma unroll
    for (int nf = 0; nf < 8; nf++)
#pragma unroll
        for (int r = 0; r < 4; r++) oacc[nf][r] = 0.0f;

    for (int kt = 0; kt < S_LEN / 64; kt++) {
        asm volatile("cp.async.wait_group 1;");
        __syncthreads();
        const uint32_t kAddr =
            smem_u32(smh + SM_K + (kt & 1) * SM_KSZ) + bLane;
        const uint32_t vAddr =
            smem_u32(smh + SM_V + (kt & 1) * SM_VSZ) + bLane;

        // ---- S = Q K^T (pipelined kfr) ----
        float sacc[8][4];
#pragma unroll
        for (int nf = 0; nf < 8; nf++)
#pragma unroll
            for (int r = 0; r < 4; r++) sacc[nf][r] = 0.0f;

        {
            uint32_t kfr[2][4];
            ldm_x4(kfr[0], kAddr);   // ks=0, np=0
#pragma unroll
            for (int idx = 0; idx < 16; idx++) {
                const int ks = idx >> 2, np = idx & 3;
                if (idx < 15) {
                    const int nks = (idx + 1) >> 2, nnp = (idx + 1) & 3;
                    ldm_x4(kfr[(idx + 1) & 1],
                           kAddr + (uint32_t)(nnp * 16 * 144) + nks * 32);
                }
                mma_f16(sacc[2 * np], qf[ks], kfr[idx & 1]);
                mma_f16(sacc[2 * np + 1], qf[ks], kfr[idx & 1] + 2);
            }
        }

        // ---- online softmax (rows g, g+8) ----
        float rmax0 = -1e30f, rmax1 = -1e30f;
#pragma unroll
        for (int nf = 0; nf < 8; nf++) {
#pragma unroll
            for (int r = 0; r < 4; r++) sacc[nf][r] *= SCALE_LOG2E;
            rmax0 = fmaxf(rmax0, fmaxf(sacc[nf][0], sacc[nf][1]));
            rmax1 = fmaxf(rmax1, fmaxf(sacc[nf][2], sacc[nf][3]));
        }
        rmax0 = fmaxf(rmax0, __shfl_xor_sync(0xffffffffu, rmax0, 1));
        rmax0 = fmaxf(rmax0, __shfl_xor_sync(0xffffffffu, rmax0, 2));
        rmax1 = fmaxf(rmax1, __shfl_xor_sync(0xffffffffu, rmax1, 1));
        rmax1 = fmaxf(rmax1, __shfl_xor_sync(0xffffffffu, rmax1, 2));

        const float mn0 = fmaxf(m0, rmax0);
        const float mn1 = fmaxf(m1, rmax1);
        const float corr0 = exp2_fast(m0 - mn0);
        const float corr1 = exp2_fast(m1 - mn1);
        m0 = mn0; m1 = mn1;

        float s0 = 0.0f, s1 = 0.0f;
        __syncwarp();
#pragma unroll
        for (int nf = 0; nf < 8; nf++) {
            float p0 = exp2_fast(sacc[nf][0] - mn0);
            float p1 = exp2_fast(sacc[nf][1] - mn0);
            float p2 = exp2_fast(sacc[nf][2] - mn1);
            float p3 = exp2_fast(sacc[nf][3] - mn1);
            s0 += p0 + p1;
            s1 += p2 + p3;
            *(__half2*)(Pw + g * LDH + nf * 8 + 2 * tig) =
                __floats2half2_rn(p0, p1);
            *(__half2*)(Pw + (g + 8) * LDH + nf * 8 + 2 * tig) =
                __floats2half2_rn(p2, p3);
        }
        s0 += __shfl_xor_sync(0xffffffffu, s0, 1);
        s0 += __shfl_xor_sync(0xffffffffu, s0, 2);
        s1 += __shfl_xor_sync(0xffffffffu, s1, 1);
        s1 += __shfl_xor_sync(0xffffffffu, s1, 2);
        l0 = l0 * corr0 + s0;
        l1 = l1 * corr1 + s1;
#pragma unroll
        for (int nf = 0; nf < 8; nf++) {
            oacc[nf][0] *= corr0; oacc[nf][1] *= corr0;
            oacc[nf][2] *= corr1; oacc[nf][3] *= corr1;
        }
        __syncwarp();

        // ---- O += P V (pf hoisted; vfr pipelined) ----
        {
            uint32_t pf[4][4];
#pragma unroll
            for (int ks = 0; ks < 4; ks++) ldm_x4(pf[ks], pAddr + ks * 32);
            uint32_t vfr[2][4];
            ldm_x4(vfr[0], vAddr);   // ks=0, np=0
#pragma unroll
            for (int idx = 0; idx < 16; idx++) {
                const int ks = idx >> 2, np = idx & 3;
                if (idx < 15) {
                    const int nks = (idx + 1) >> 2, nnp = (idx + 1) & 3;
                    ldm_x4(vfr[(idx + 1) & 1],
                           vAddr + (uint32_t)(nnp * 16 * 144) + nks * 32);
                }
                mma_f16(oacc[2 * np], pf[ks], vfr[idx & 1]);
                mma_f16(oacc[2 * np + 1], pf[ks], vfr[idx & 1] + 2);
            }
        }

        __syncthreads();
        if (kt + 2 < S_LEN / 64) LOAD_KV(kt + 2, kt & 1);
        asm volatile("cp.async.commit_group;");
    }

    // ---- epilogue: fp16 out for the out-projection ----
    const float inv0 = 1.0f / l0;
    const float inv1 = 1.0f / l1;
    const int row0 = q0 + wid * 16 + g;
    __half* od = outp + (size_t)(b * S_LEN + row0) * HID + h * DH;
#pragma unroll
    for (int nf = 0; nf < 8; nf++) {
        const int col = nf * 8 + 2 * tig;
        *(__half2*)(od + col) =
            __floats2half2_rn(oacc[nf][0] * inv0, oacc[nf][1] * inv0);
        *(__half2*)(od + (size_t)8 * HID + col) =
            __floats2half2_rn(oacc[nf][2] * inv1, oacc[nf][3] * inv1);
    }
}

// ---------------------------------------------------------------------------
// Launch
// ---------------------------------------------------------------------------
extern "C" void kernel_launch(void* const* d_in, const int* in_sizes, int n_in,
                              void* d_out, int out_size)
{
    const float* x     = (const float*)d_in[0];
    const float* w_qkv = (const float*)d_in[1];
    const float* w_out = (const float*)d_in[2];
    const float* b_out = (const float*)d_in[3];
    float* out = (float*)d_out;

    __half *qkv_p, *vt_p, *att_p, *x_p, *wqkv_p, *wout_p;
    cudaGetSymbolAddress((void**)&qkv_p, g_qkv_h);
    cudaGetSymbolAddress((void**)&vt_p, g_vt_h);
    cudaGetSymbolAddress((void**)&att_p, g_att_h);
    cudaGetSymbolAddress((void**)&x_p, g_x_h);
    cudaGetSymbolAddress((void**)&wqkv_p, g_wqkv_h);
    cudaGetSymbolAddress((void**)&wout_p, g_wout_h);

    const int gemm_smem = NSTAGE * 2 * STAGEH * 2;  // 110592 bytes
    cudaFuncSetAttribute(gemm_h_kernel,
                         cudaFuncAttributeMaxDynamicSharedMemorySize, gemm_smem);
    cudaFuncSetAttribute(attn_h_kernel,
                         cudaFuncAttributeMaxDynamicSharedMemorySize, SMEM_ATT);

    // 0) fp32 -> fp16 (rn) inputs
    {
        int n1 = MTOT * HID;
        int n2 = 3 * HID * HID;
        int n3 = HID * HID;
        to_half_kernel<<<(n1 / 4 + 255) / 256, 256>>>(x, x_p, n1);
        to_half_kernel<<<(n2 / 4 + 255) / 256, 256>>>(w_qkv, wqkv_p, n2);
        to_half_kernel<<<(n3 / 4 + 255) / 256, 256>>>(w_out, wout_p, n3);
    }

    // 1) qkv = x @ w_qkv^T  (q,k -> g_qkv_h; v -> g_vt_h transposed)
    gemm_h_kernel<<<dim3(3 * HID / BN, MTOT / BM), 256, gemm_smem>>>(
        x_p, wqkv_p, nullptr, nullptr, qkv_p, vt_p, MTOT, 3 * HID, HID, 1);

    // 2) fp16 flash attention
    attn_h_kernel<<<dim3(S_LEN / 64, BATCH * NH), 128, SMEM_ATT>>>(
        qkv_p, vt_p, att_p);

    // 3) out = att @ w_out^T + b_out  (fp32 output)
    gemm_h_kernel<<<dim3(HID / BN, MTOT / BM), 256, gemm_smem>>>(
        att_p, wout_p, b_out, out, nullptr, nullptr, MTOT, HID, HID, 0);
}